// round 10
// baseline (speedup 1.0000x reference)
#include <cuda_runtime.h>
#include <math.h>

typedef unsigned long long ull;

#define CONF_THR 0.3f
#define NMS_THRV 0.5f
#define MAXDET 100

// ---------------- scratch (static device arrays; no allocation) ----------------
__device__ float g_act0[256 * 256 * 49];
__device__ float g_act1[256 * 256 * 49];
__device__ float g_boxpred[256 * 588 * 4];
__device__ float g_scores[256 * 588];
// transposed, pair-duplicated {w,w} u64 weights (padded)
__device__ ull g_wt1[512 * 256 + 256];
__device__ ull g_wt2[2304 * 256 + 2560];
__device__ ull g_wt3[2304 * 256 + 2560];
__device__ ull g_wt4[2304 * 256 + 2560];
__device__ ull g_wth[2304 * 64 + 640];

// ---------------- packed f32x2 helpers ----------------
__device__ __forceinline__ ull fma2(ull a, ull b, ull c) {
    ull d;
    asm("fma.rn.f32x2 %0, %1, %2, %3;" : "=l"(d) : "l"(a), "l"(b), "l"(c));
    return d;
}
__device__ __forceinline__ ull pack2(float lo, float hi) {
    unsigned l = __float_as_uint(lo), h = __float_as_uint(hi);
    ull d;
    asm("mov.b64 %0, {%1, %2};" : "=l"(d) : "r"(l), "r"(h));
    return d;
}
__device__ __forceinline__ void unpack2(ull v, float& lo, float& hi) {
    unsigned l, h;
    asm("mov.b64 {%0, %1}, %2;" : "=r"(l), "=r"(h) : "l"(v));
    lo = __uint_as_float(l);
    hi = __uint_as_float(h);
}

// ---------------- XLA logistic: 0.5 + 0.5*tanh(0.5*x), XLA fast-tanh f32 ----------------
__device__ __forceinline__ float xla_tanh(float x) {
    float ax = fabsf(x);
    float xc = fminf(fmaxf(x, -9.0f), 9.0f);
    float x2 = xc * xc;
    float p = fmaf(x2, -2.76076847742355e-16f, 2.00018790482477e-13f);
    p = fmaf(x2, p, -8.60467152213735e-11f);
    p = fmaf(x2, p, 5.12229709037114e-08f);
    p = fmaf(x2, p, 1.48572235717979e-05f);
    p = fmaf(x2, p, 6.37261928875436e-04f);
    p = fmaf(x2, p, 4.89352455891786e-03f);
    p = xc * p;
    float q = fmaf(x2, 1.19825839466702e-06f, 1.18534705686654e-04f);
    q = fmaf(x2, q, 2.26843463243900e-03f);
    q = fmaf(x2, q, 4.89352518554385e-03f);
    float r = p / q;
    return (ax < 0.0004f) ? x : r;
}
__device__ __forceinline__ float xla_sigmoid(float x) {
    float t = xla_tanh(0.5f * x);
    return 0.5f + 0.5f * t;
}

// =====================================================================
// Kernel 0: weight transpose + {w,w} duplication.
// =====================================================================
#define NT1 (512 * 256)
#define NT3 (2304 * 256)
#define NTH (2304 * 64)
#define NT_TOTAL (NT1 + 3 * NT3 + NTH)

__global__ void __launch_bounds__(256) k_wt(
    const float* __restrict__ w1, const float* __restrict__ w2,
    const float* __restrict__ w3, const float* __restrict__ w4,
    const float* __restrict__ wcls, const float* __restrict__ wbox)
{
    int idx = blockIdx.x * 256 + threadIdx.x;
    if (idx < NT1) {
        int oc = idx & 255, ic = idx >> 8;
        float v = w1[oc * 512 + ic];
        g_wt1[idx] = pack2(v, v);
        return;
    }
    idx -= NT1;
    if (idx < NT3) {
        int oc = idx & 255, k = idx >> 8;
        float v = w2[oc * 2304 + k];
        g_wt2[idx] = pack2(v, v);
        return;
    }
    idx -= NT3;
    if (idx < NT3) {
        int oc = idx & 255, k = idx >> 8;
        float v = w3[oc * 2304 + k];
        g_wt3[idx] = pack2(v, v);
        return;
    }
    idx -= NT3;
    if (idx < NT3) {
        int oc = idx & 255, k = idx >> 8;
        float v = w4[oc * 2304 + k];
        g_wt4[idx] = pack2(v, v);
        return;
    }
    idx -= NT3;
    if (idx < NTH) {
        int slot = idx & 63, k = idx >> 6;
        float v = 0.0f;
        if (slot < 12) v = wcls[slot * 2304 + k];
        else if (slot < 60) v = wbox[(slot - 12) * 2304 + k];
        g_wth[idx] = pack2(v, v);
    }
}

// =====================================================================
// Kernel 1: 1x1 conv (512->256) + BN + ReLU.
// Half-image CTAs by position. smem [512][26] (53.2KB) -> 4 CTA/SM.
// 256 threads: ocpair = tid&127, sub = tid>>7. Writes clamped to half.
// =====================================================================
#define SM1_BYTES (512 * 26 * 4)

__global__ void __launch_bounds__(256, 4) k_conv1x1(
    const float* __restrict__ in, const ull* __restrict__ wt,
    const float* __restrict__ b, const float* __restrict__ g,
    const float* __restrict__ be, const float* __restrict__ mu,
    const float* __restrict__ var, float* __restrict__ out)
{
    extern __shared__ float sm[];
    const int blk = blockIdx.x;
    const int bidx = blk >> 1;
    const int half = blk & 1;
    const int tid = threadIdx.x;
    const float* inb = in + (size_t)bidx * 512 * 49;
    const int p0 = half ? 24 : 0;
    const int np = half ? 25 : 24;
    const int plimit = p0 + np;

    for (int k = tid; k < 512 * 13; k += 256) ((ull*)sm)[k] = 0ull;
    __syncthreads();
    for (int k = tid; k < 512 * np; k += 256) {
        int ic = k / np, p = k % np;
        sm[ic * 26 + p] = inb[ic * 49 + p0 + p];
    }
    __syncthreads();

    const int op = tid & 127;
    const int sub = tid >> 7;
    const int oc0 = op * 2;
    const int pp0 = sub ? 7 : 0;
    const int pn = sub ? 6 : 7;

    ull acc[2][7];
#pragma unroll
    for (int j = 0; j < 2; j++)
#pragma unroll
        for (int p = 0; p < 7; p++) acc[j][p] = 0ull;

#pragma unroll 1
    for (int ic = 0; ic < 512; ic++) {
        ulonglong2 wv = *(const ulonglong2*)(wt + ic * 256 + oc0);
        const ull* row = (const ull*)(sm + ic * 26) + pp0;
#pragma unroll
        for (int p = 0; p < 7; p++) {
            if (sub == 0 || p < 6) {
                ull x = row[p];
                acc[0][p] = fma2(wv.x, x, acc[0][p]);
                acc[1][p] = fma2(wv.y, x, acc[1][p]);
            }
        }
    }

#pragma unroll
    for (int j = 0; j < 2; j++) {
        int oc = oc0 + j;
        float inv = g[oc] * rsqrtf(var[oc] + 1e-5f);
        float sh = (b[oc] - mu[oc]) * inv + be[oc];
        float* outp = out + (size_t)bidx * 256 * 49 + oc * 49;
#pragma unroll
        for (int p = 0; p < 7; p++) {
            if (p < pn) {
                float vlo, vhi;
                unpack2(acc[j][p], vlo, vhi);
                int pos = p0 + 2 * (pp0 + p);
                if (pos < plimit) outp[pos] = fmaxf(vlo * inv + sh, 0.0f);
                if (pos + 1 < plimit) outp[pos + 1] = fmaxf(vhi * inv + sh, 0.0f);
            }
        }
    }
}

// =====================================================================
// Kernel 2: 3x3 conv (256->256, pad 1) + BN + ReLU.
// grid 1024: (image, colhalf, ochalf). 128-thread CTAs (one oc each),
// E/O dual tile, two-phase ic (tile [128][7][10] = 35KB) -> 6 CTA/SM,
// near-perfect wave balance (crit 7 quarter-units vs 8 before).
// FMA order ic->dy->dx preserved (bit-exact).
// =====================================================================
#define SM3_BYTES (128 * 70 * 4)

__global__ void __launch_bounds__(128, 6) k_conv3x3(
    const float* __restrict__ in, const ull* __restrict__ wt,
    const float* __restrict__ b, const float* __restrict__ g,
    const float* __restrict__ be, const float* __restrict__ mu,
    const float* __restrict__ var, float* __restrict__ out)
{
    extern __shared__ float sm[];
    const int blk = blockIdx.x;
    const int bidx = blk >> 2;
    const int half = (blk >> 1) & 1;
    const int och = (blk & 1) * 128;
    const int tid = threadIdx.x;
    const float* inb = in + (size_t)bidx * 256 * 49;

    const int cw = half ? 4 : 5;
    const int coff = half ? 0 : 1;
    const int xoff = half ? 3 : 0;

    for (int k = tid; k < 128 * 35; k += 128) ((ull*)sm)[k] = 0ull;

    const int oc = och + tid;
    ull acc[7][2];
#pragma unroll
    for (int y = 0; y < 7; y++) {
        acc[y][0] = 0ull;
        acc[y][1] = 0ull;
    }

    const int nload = 128 * 7 * cw;

#pragma unroll 1
    for (int ph = 0; ph < 2; ph++) {
        __syncthreads();
        const float* inph = inb + ph * 128 * 49;
        for (int k = tid; k < nload; k += 128) {
            int icl = k / (7 * cw), rem = k % (7 * cw);
            int r = rem / cw, j = rem % cw;
            float v = inph[icl * 49 + r * 7 + xoff + j];
            int base = icl * 70 + r * 10;
            int cpos = coff + j;
            sm[base + cpos] = v;                                      // E: c0..c5
            if (cpos >= 1 && cpos <= 4) sm[base + 6 + (cpos - 1)] = v;   // O: c1..c4
        }
        __syncthreads();

        const ull* wtp = wt + (size_t)ph * 128 * 9 * 256 + oc;
#pragma unroll 1
        for (int icl = 0; icl < 128; icl++) {
            ull wc[9];
#pragma unroll
            for (int t = 0; t < 9; t++) wc[t] = __ldg(wtp + (icl * 9 + t) * 256);

            const ull* rowb = (const ull*)sm + icl * 35;
#pragma unroll
            for (int r = 0; r < 7; r++) {
                ull E0 = rowb[r * 5 + 0], E1 = rowb[r * 5 + 1], E2 = rowb[r * 5 + 2];
                ull O0 = rowb[r * 5 + 3], O1 = rowb[r * 5 + 4];
#pragma unroll
                for (int dy = 0; dy < 3; dy++) {
                    int yy = r - dy + 1;
                    if (yy < 0 || yy > 6) continue;
                    acc[yy][0] = fma2(wc[dy * 3 + 0], E0, acc[yy][0]);
                    acc[yy][0] = fma2(wc[dy * 3 + 1], O0, acc[yy][0]);
                    acc[yy][0] = fma2(wc[dy * 3 + 2], E1, acc[yy][0]);
                    acc[yy][1] = fma2(wc[dy * 3 + 0], E1, acc[yy][1]);
                    acc[yy][1] = fma2(wc[dy * 3 + 1], O1, acc[yy][1]);
                    acc[yy][1] = fma2(wc[dy * 3 + 2], E2, acc[yy][1]);
                }
            }
        }
    }

    float inv = g[oc] * rsqrtf(var[oc] + 1e-5f);
    float sh = (b[oc] - mu[oc]) * inv + be[oc];
    float* outp = out + (size_t)bidx * 256 * 49 + oc * 49;
    const int xbase = half ? 4 : 0;
#pragma unroll
    for (int yy = 0; yy < 7; yy++) {
#pragma unroll
        for (int k2 = 0; k2 < 2; k2++) {
            float vlo, vhi;
            unpack2(acc[yy][k2], vlo, vhi);
            int x = xbase + 2 * k2;
            outp[yy * 7 + x] = fmaxf(vlo * inv + sh, 0.0f);
            if (x + 1 < 7) outp[yy * 7 + x + 1] = fmaxf(vhi * inv + sh, 0.0f);
        }
    }
}

// =====================================================================
// Kernel 3: heads — 3x3 conv into 12 cls + 48 box channels (+bias).
// Half-image CTAs by row, E/O dual-layout rows, TWO-PHASE over ic:
// tile [128 ic][6 rows][18 floats] = 54KB -> 4 CTA/SM, grid 512 = 1 wave.
// Row layout: E0..E4 (floats 0..9; value x at offset x+1), O0..O3
// (floats 10..17; value x at offset 10+x). Same tap order as before
// (E0,O0,E1 / E1,O1,E2 / E2,O2,E3 / E3,O3,E4) -> bit-exact.
// =====================================================================
#define SMH_BYTES (128 * 108 * 4)

__global__ void __launch_bounds__(256, 4) k_heads(
    const float* __restrict__ in, const ull* __restrict__ wt,
    const float* __restrict__ bcls, const float* __restrict__ bbox,
    float* __restrict__ boxpred, float* __restrict__ scores)
{
    extern __shared__ float sm[];
    const int blk = blockIdx.x;
    const int bidx = blk >> 1;
    const int half = blk & 1;
    const int tid = threadIdx.x;
    const float* inb = in + (size_t)bidx * 256 * 49;
    const int base = half ? 3 : -1;      // smem row r = input row base+r
    const int outbase = half ? 4 : 0;

    // zero once; zero slots fixed across phases
    for (int k = tid; k < 128 * 54; k += 256) ((ull*)sm)[k] = 0ull;

    const int slot = tid & 63;
    const int lr = tid >> 6;      // 0..3
    const int yout = outbase + lr;
    const bool valid = (yout < 7);

    ull acc[4];
#pragma unroll
    for (int k2 = 0; k2 < 4; k2++) acc[k2] = 0ull;

#pragma unroll 1
    for (int ph = 0; ph < 2; ph++) {
        __syncthreads();
        const float* inph = inb + ph * 128 * 49;
        for (int k = tid; k < 128 * 42; k += 256) {
            int icl = k / 42, rem = k % 42, r = rem / 7, x = rem % 7;
            int y = base + r;
            if (y >= 0 && y <= 6) {
                float v = inph[icl * 49 + y * 7 + x];
                int rbase = icl * 108 + r * 18;
                sm[rbase + x + 1] = v;        // E slots
                sm[rbase + 10 + x] = v;       // O slots
            }
        }
        __syncthreads();

        if (valid) {
            const ull* wtp = wt + (size_t)ph * 128 * 9 * 64 + slot;
#pragma unroll 1
            for (int icl = 0; icl < 128; icl++) {
                ull wc[9];
#pragma unroll
                for (int t = 0; t < 9; t++) wc[t] = __ldg(wtp + (icl * 9 + t) * 64);

#pragma unroll
                for (int dy = 0; dy < 3; dy++) {
                    int r = lr + dy;
                    const ull* rp = (const ull*)(sm + icl * 108 + r * 18);
                    ull E0 = rp[0], E1 = rp[1], E2 = rp[2], E3 = rp[3], E4 = rp[4];
                    ull O0 = rp[5], O1 = rp[6], O2 = rp[7], O3 = rp[8];
                    acc[0] = fma2(wc[dy * 3 + 0], E0, acc[0]);
                    acc[0] = fma2(wc[dy * 3 + 1], O0, acc[0]);
                    acc[0] = fma2(wc[dy * 3 + 2], E1, acc[0]);
                    acc[1] = fma2(wc[dy * 3 + 0], E1, acc[1]);
                    acc[1] = fma2(wc[dy * 3 + 1], O1, acc[1]);
                    acc[1] = fma2(wc[dy * 3 + 2], E2, acc[1]);
                    acc[2] = fma2(wc[dy * 3 + 0], E2, acc[2]);
                    acc[2] = fma2(wc[dy * 3 + 1], O2, acc[2]);
                    acc[2] = fma2(wc[dy * 3 + 2], E3, acc[2]);
                    acc[3] = fma2(wc[dy * 3 + 0], E3, acc[3]);
                    acc[3] = fma2(wc[dy * 3 + 1], O3, acc[3]);
                    acc[3] = fma2(wc[dy * 3 + 2], E4, acc[3]);
                }
            }
        }
    }

    if (!valid) return;

    if (slot < 12) {
        float bv = bcls[slot];
#pragma unroll
        for (int k2 = 0; k2 < 4; k2++) {
            float vlo, vhi;
            unpack2(acc[k2], vlo, vhi);
            int x = 2 * k2;
            int p0 = yout * 7 + x;
            scores[(size_t)bidx * 588 + p0 * 12 + slot] = xla_sigmoid(vlo + bv);
            if (x + 1 < 7)
                scores[(size_t)bidx * 588 + (p0 + 1) * 12 + slot] = xla_sigmoid(vhi + bv);
        }
    } else if (slot < 60) {
        int c = slot - 12;
        int a = c >> 2, coord = c & 3;
        float bv = bbox[c];
#pragma unroll
        for (int k2 = 0; k2 < 4; k2++) {
            float vlo, vhi;
            unpack2(acc[k2], vlo, vhi);
            int x = 2 * k2;
            int p0 = yout * 7 + x;
            boxpred[((size_t)bidx * 588 + p0 * 12 + a) * 4 + coord] = vlo + bv;
            if (x + 1 < 7)
                boxpred[((size_t)bidx * 588 + (p0 + 1) * 12 + a) * 4 + coord] = vhi + bv;
        }
    }
}

// =====================================================================
// Kernel 4: decode + exact greedy NMS. One block (256 thr) per image.
// =====================================================================
#define SMN_BYTES (6468 * 4 + 588 * 8 + 588 * 19 * 4 + 101 * 4)

__global__ void __launch_bounds__(256) k_nms(
    const float* __restrict__ boxpred, const float* __restrict__ scores,
    float* __restrict__ out)
{
    extern __shared__ float sm[];
    float* dbx = sm;
    float* dsc = dbx + 2352;
    float* sbx = dsc + 588;
    float* ss = sbx + 2352;
    float* sar = ss + 588;
    ull* keys = (ull*)(sar + 588);
    unsigned* adj = (unsigned*)(keys + 588);
    int* keepL = (int*)(adj + 588 * 19);
    int* keepCnt = keepL + 100;

    const int bidx = blockIdx.x;
    const int tid = threadIdx.x;
    const float* bp = boxpred + (size_t)bidx * 588 * 4;
    const float* sc = scores + (size_t)bidx * 588;

    const float SCALES[4] = {0.3f, 0.5f, 0.7f, 0.9f};
    const float RATIOS[3] = {0.7f, 1.0f, 1.3f};

    for (int i = tid; i < 588; i += 256) {
        int p = i / 12, a = i % 12;
        int si = a / 3, ri = a % 3;
        float cx = ((float)(p / 7) + 0.5f) / 7.0f;
        float cy = ((float)(p % 7) + 0.5f) / 7.0f;
        float rt = sqrtf(RATIOS[ri]);
        float ws = SCALES[si] * rt;
        float hs = SCALES[si] / rt;
        float hw = ws * 0.5f, hh = hs * 0.5f;
        float a0 = cx - hw, a1 = cy - hh, a2 = cx + hw, a3 = cy + hh;
        float acx = (a0 + a2) * 0.5f, acy = (a1 + a3) * 0.5f;
        float aszx = a2 - a0, aszy = a3 - a1;
        float t0 = bp[i * 4 + 0], t1 = bp[i * 4 + 1];
        float t2 = bp[i * 4 + 2], t3 = bp[i * 4 + 3];
        float pcx = t0 * aszx + acx;
        float pcy = t1 * aszy + acy;
        float psx = expf(t2) * aszx;
        float psy = expf(t3) * aszy;
        dbx[i * 4 + 0] = pcx - psx * 0.5f;
        dbx[i * 4 + 1] = pcy - psy * 0.5f;
        dbx[i * 4 + 2] = pcx + psx * 0.5f;
        dbx[i * 4 + 3] = pcy + psy * 0.5f;
        float s = sc[i];
        dsc[i] = s;
        keys[i] = (((ull)(0xFFFFFFFFu - __float_as_uint(s))) << 32) | (unsigned)i;
    }
    __syncthreads();

    for (int i = tid; i < 588; i += 256) {
        ull ki = keys[i];
        int r = 0;
        for (int j = 0; j < 588; j++) r += (keys[j] < ki) ? 1 : 0;
        ss[r] = dsc[i];
        float x0 = dbx[i * 4 + 0], y0 = dbx[i * 4 + 1];
        float x1 = dbx[i * 4 + 2], y1 = dbx[i * 4 + 3];
        sbx[r * 4 + 0] = x0;
        sbx[r * 4 + 1] = y0;
        sbx[r * 4 + 2] = x1;
        sbx[r * 4 + 3] = y1;
        sar[r] = (x1 - x0) * (y1 - y0);
    }
    __syncthreads();

    for (int t = tid; t < 588 * 19; t += 256) {
        int i = t / 19, wdi = t % 19;
        unsigned word = 0;
        if (ss[i] > CONF_THR) {
            float ax0 = sbx[i * 4 + 0], ay0 = sbx[i * 4 + 1];
            float ax1 = sbx[i * 4 + 2], ay1 = sbx[i * 4 + 3];
            float aar = sar[i];
            int j0 = wdi * 32;
            int jend = min(588 - j0, 32);
            for (int bb = 0; bb < jend; bb++) {
                int j = j0 + bb;
                float lx = fmaxf(ax0, sbx[j * 4 + 0]);
                float ly = fmaxf(ay0, sbx[j * 4 + 1]);
                float rx = fminf(ax1, sbx[j * 4 + 2]);
                float ry = fminf(ay1, sbx[j * 4 + 3]);
                float iw = fmaxf(rx - lx, 0.0f);
                float ih = fmaxf(ry - ly, 0.0f);
                float inter = iw * ih;
                float iou = inter / (aar + sar[j] - inter + 1e-9f);
                if (iou > NMS_THRV) word |= (1u << bb);
            }
        }
        adj[i * 19 + wdi] = word;
    }
    __syncthreads();

    if (tid == 0) {
        unsigned sup[19];
#pragma unroll
        for (int w2 = 0; w2 < 19; w2++) sup[w2] = 0u;
        int cnt = 0;
        for (int i = 0; i < 588; i++) {
            if (!(ss[i] > CONF_THR)) break;
            if ((sup[i >> 5] >> (i & 31)) & 1u) continue;
            keepL[cnt++] = i;
            if (cnt == MAXDET) break;
            int w0 = i >> 5, bpos = i & 31;
            unsigned m0 = (bpos == 31) ? 0u : (0xFFFFFFFFu << (bpos + 1));
            sup[w0] |= adj[i * 19 + w0] & m0;
            for (int w2 = w0 + 1; w2 < 19; w2++) sup[w2] |= adj[i * 19 + w2];
        }
        *keepCnt = cnt;
    }
    __syncthreads();

    int cnt = *keepCnt;
    for (int r = tid; r < MAXDET; r += 256) {
        float* o = out + ((size_t)bidx * MAXDET + r) * 6;
        if (r < cnt) {
            int i = keepL[r];
            o[0] = sbx[i * 4 + 0];
            o[1] = sbx[i * 4 + 1];
            o[2] = sbx[i * 4 + 2];
            o[3] = sbx[i * 4 + 3];
            o[4] = ss[i];
            o[5] = 1.0f;
        } else {
            o[0] = 0.0f; o[1] = 0.0f; o[2] = 0.0f;
            o[3] = 0.0f; o[4] = 0.0f; o[5] = 0.0f;
        }
    }
}

// =====================================================================
// launcher
// =====================================================================
extern "C" void kernel_launch(void* const* d_in, const int* in_sizes, int n_in,
                              void* d_out, int out_size)
{
    (void)in_sizes; (void)n_in; (void)out_size;

    const float* features = (const float*)d_in[0];
    const float* w1 = (const float*)d_in[1];
    const float* b1 = (const float*)d_in[2];
    const float* g1 = (const float*)d_in[3];
    const float* be1 = (const float*)d_in[4];
    const float* mu1 = (const float*)d_in[5];
    const float* var1 = (const float*)d_in[6];
    const float* w2 = (const float*)d_in[7];
    const float* b2 = (const float*)d_in[8];
    const float* g2 = (const float*)d_in[9];
    const float* be2 = (const float*)d_in[10];
    const float* mu2 = (const float*)d_in[11];
    const float* var2 = (const float*)d_in[12];
    const float* w3 = (const float*)d_in[13];
    const float* b3 = (const float*)d_in[14];
    const float* g3 = (const float*)d_in[15];
    const float* be3 = (const float*)d_in[16];
    const float* mu3 = (const float*)d_in[17];
    const float* var3 = (const float*)d_in[18];
    const float* w4 = (const float*)d_in[19];
    const float* b4 = (const float*)d_in[20];
    const float* g4 = (const float*)d_in[21];
    const float* be4 = (const float*)d_in[22];
    const float* mu4 = (const float*)d_in[23];
    const float* var4 = (const float*)d_in[24];
    const float* w_cls = (const float*)d_in[25];
    const float* b_cls = (const float*)d_in[26];
    const float* w_box = (const float*)d_in[27];
    const float* b_box = (const float*)d_in[28];
    float* out = (float*)d_out;

    float *act0, *act1, *bpred, *scr;
    ull *wt1, *wt2, *wt3, *wt4, *wth;
    cudaGetSymbolAddress((void**)&act0, g_act0);
    cudaGetSymbolAddress((void**)&act1, g_act1);
    cudaGetSymbolAddress((void**)&bpred, g_boxpred);
    cudaGetSymbolAddress((void**)&scr, g_scores);
    cudaGetSymbolAddress((void**)&wt1, g_wt1);
    cudaGetSymbolAddress((void**)&wt2, g_wt2);
    cudaGetSymbolAddress((void**)&wt3, g_wt3);
    cudaGetSymbolAddress((void**)&wt4, g_wt4);
    cudaGetSymbolAddress((void**)&wth, g_wth);

    cudaFuncSetAttribute(k_conv1x1, cudaFuncAttributeMaxDynamicSharedMemorySize, SM1_BYTES);
    cudaFuncSetAttribute(k_conv3x3, cudaFuncAttributeMaxDynamicSharedMemorySize, SM3_BYTES);
    cudaFuncSetAttribute(k_heads, cudaFuncAttributeMaxDynamicSharedMemorySize, SMH_BYTES);
    cudaFuncSetAttribute(k_nms, cudaFuncAttributeMaxDynamicSharedMemorySize, SMN_BYTES);

    k_wt<<<(NT_TOTAL + 255) / 256, 256>>>(w1, w2, w3, w4, w_cls, w_box);
    k_conv1x1<<<512, 256, SM1_BYTES>>>(features, wt1, b1, g1, be1, mu1, var1, act0);
    k_conv3x3<<<1024, 128, SM3_BYTES>>>(act0, wt2, b2, g2, be2, mu2, var2, act1);
    k_conv3x3<<<1024, 128, SM3_BYTES>>>(act1, wt3, b3, g3, be3, mu3, var3, act0);
    k_conv3x3<<<1024, 128, SM3_BYTES>>>(act0, wt4, b4, g4, be4, mu4, var4, act1);
    k_heads<<<512, 256, SMH_BYTES>>>(act1, wth, b_cls, b_box, bpred, scr);
    k_nms<<<256, 256, SMN_BYTES>>>(bpred, scr, out);
}

// round 11
// speedup vs baseline: 1.0229x; 1.0229x over previous
#include <cuda_runtime.h>
#include <math.h>

typedef unsigned long long ull;

#define CONF_THR 0.3f
#define NMS_THRV 0.5f
#define MAXDET 100

// ---------------- scratch (static device arrays; no allocation) ----------------
__device__ float g_act0[256 * 256 * 49];
__device__ float g_act1[256 * 256 * 49];
__device__ float g_boxpred[256 * 588 * 4];
__device__ float g_scores[256 * 588];
// transposed, pair-duplicated {w,w} u64 weights (padded)
__device__ ull g_wt1[512 * 256 + 256];
__device__ ull g_wt2[2304 * 256 + 2560];
__device__ ull g_wt3[2304 * 256 + 2560];
__device__ ull g_wt4[2304 * 256 + 2560];
__device__ ull g_wth[2304 * 64 + 640];

// ---------------- packed f32x2 helpers ----------------
__device__ __forceinline__ ull fma2(ull a, ull b, ull c) {
    ull d;
    asm("fma.rn.f32x2 %0, %1, %2, %3;" : "=l"(d) : "l"(a), "l"(b), "l"(c));
    return d;
}
__device__ __forceinline__ ull pack2(float lo, float hi) {
    unsigned l = __float_as_uint(lo), h = __float_as_uint(hi);
    ull d;
    asm("mov.b64 %0, {%1, %2};" : "=l"(d) : "r"(l), "r"(h));
    return d;
}
__device__ __forceinline__ void unpack2(ull v, float& lo, float& hi) {
    unsigned l, h;
    asm("mov.b64 {%0, %1}, %2;" : "=r"(l), "=r"(h) : "l"(v));
    lo = __uint_as_float(l);
    hi = __uint_as_float(h);
}

// ---------------- XLA logistic: 0.5 + 0.5*tanh(0.5*x), XLA fast-tanh f32 ----------------
__device__ __forceinline__ float xla_tanh(float x) {
    float ax = fabsf(x);
    float xc = fminf(fmaxf(x, -9.0f), 9.0f);
    float x2 = xc * xc;
    float p = fmaf(x2, -2.76076847742355e-16f, 2.00018790482477e-13f);
    p = fmaf(x2, p, -8.60467152213735e-11f);
    p = fmaf(x2, p, 5.12229709037114e-08f);
    p = fmaf(x2, p, 1.48572235717979e-05f);
    p = fmaf(x2, p, 6.37261928875436e-04f);
    p = fmaf(x2, p, 4.89352455891786e-03f);
    p = xc * p;
    float q = fmaf(x2, 1.19825839466702e-06f, 1.18534705686654e-04f);
    q = fmaf(x2, q, 2.26843463243900e-03f);
    q = fmaf(x2, q, 4.89352518554385e-03f);
    float r = p / q;
    return (ax < 0.0004f) ? x : r;
}
__device__ __forceinline__ float xla_sigmoid(float x) {
    float t = xla_tanh(0.5f * x);
    return 0.5f + 0.5f * t;
}

// =====================================================================
// Kernel 0: weight transpose + {w,w} duplication.
// =====================================================================
#define NT1 (512 * 256)
#define NT3 (2304 * 256)
#define NTH (2304 * 64)
#define NT_TOTAL (NT1 + 3 * NT3 + NTH)

__global__ void __launch_bounds__(256) k_wt(
    const float* __restrict__ w1, const float* __restrict__ w2,
    const float* __restrict__ w3, const float* __restrict__ w4,
    const float* __restrict__ wcls, const float* __restrict__ wbox)
{
    int idx = blockIdx.x * 256 + threadIdx.x;
    if (idx < NT1) {
        int oc = idx & 255, ic = idx >> 8;
        float v = w1[oc * 512 + ic];
        g_wt1[idx] = pack2(v, v);
        return;
    }
    idx -= NT1;
    if (idx < NT3) {
        int oc = idx & 255, k = idx >> 8;
        float v = w2[oc * 2304 + k];
        g_wt2[idx] = pack2(v, v);
        return;
    }
    idx -= NT3;
    if (idx < NT3) {
        int oc = idx & 255, k = idx >> 8;
        float v = w3[oc * 2304 + k];
        g_wt3[idx] = pack2(v, v);
        return;
    }
    idx -= NT3;
    if (idx < NT3) {
        int oc = idx & 255, k = idx >> 8;
        float v = w4[oc * 2304 + k];
        g_wt4[idx] = pack2(v, v);
        return;
    }
    idx -= NT3;
    if (idx < NTH) {
        int slot = idx & 63, k = idx >> 6;
        float v = 0.0f;
        if (slot < 12) v = wcls[slot * 2304 + k];
        else if (slot < 60) v = wbox[(slot - 12) * 2304 + k];
        g_wth[idx] = pack2(v, v);
    }
}

// =====================================================================
// Kernel 1: 1x1 conv (512->256) + BN + ReLU.
// Half-image CTAs by position. smem [512][26] (53.2KB) -> 4 CTA/SM.
// 256 threads: ocpair = tid&127, sub = tid>>7. Writes clamped to half.
// =====================================================================
#define SM1_BYTES (512 * 26 * 4)

__global__ void __launch_bounds__(256, 4) k_conv1x1(
    const float* __restrict__ in, const ull* __restrict__ wt,
    const float* __restrict__ b, const float* __restrict__ g,
    const float* __restrict__ be, const float* __restrict__ mu,
    const float* __restrict__ var, float* __restrict__ out)
{
    extern __shared__ float sm[];
    const int blk = blockIdx.x;
    const int bidx = blk >> 1;
    const int half = blk & 1;
    const int tid = threadIdx.x;
    const float* inb = in + (size_t)bidx * 512 * 49;
    const int p0 = half ? 24 : 0;
    const int np = half ? 25 : 24;
    const int plimit = p0 + np;

    for (int k = tid; k < 512 * 13; k += 256) ((ull*)sm)[k] = 0ull;
    __syncthreads();
    for (int k = tid; k < 512 * np; k += 256) {
        int ic = k / np, p = k % np;
        sm[ic * 26 + p] = inb[ic * 49 + p0 + p];
    }
    __syncthreads();

    const int op = tid & 127;
    const int sub = tid >> 7;
    const int oc0 = op * 2;
    const int pp0 = sub ? 7 : 0;
    const int pn = sub ? 6 : 7;

    ull acc[2][7];
#pragma unroll
    for (int j = 0; j < 2; j++)
#pragma unroll
        for (int p = 0; p < 7; p++) acc[j][p] = 0ull;

#pragma unroll 1
    for (int ic = 0; ic < 512; ic++) {
        ulonglong2 wv = *(const ulonglong2*)(wt + ic * 256 + oc0);
        const ull* row = (const ull*)(sm + ic * 26) + pp0;
#pragma unroll
        for (int p = 0; p < 7; p++) {
            if (sub == 0 || p < 6) {
                ull x = row[p];
                acc[0][p] = fma2(wv.x, x, acc[0][p]);
                acc[1][p] = fma2(wv.y, x, acc[1][p]);
            }
        }
    }

#pragma unroll
    for (int j = 0; j < 2; j++) {
        int oc = oc0 + j;
        float inv = g[oc] * rsqrtf(var[oc] + 1e-5f);
        float sh = (b[oc] - mu[oc]) * inv + be[oc];
        float* outp = out + (size_t)bidx * 256 * 49 + oc * 49;
#pragma unroll
        for (int p = 0; p < 7; p++) {
            if (p < pn) {
                float vlo, vhi;
                unpack2(acc[j][p], vlo, vhi);
                int pos = p0 + 2 * (pp0 + p);
                if (pos < plimit) outp[pos] = fmaxf(vlo * inv + sh, 0.0f);
                if (pos + 1 < plimit) outp[pos + 1] = fmaxf(vhi * inv + sh, 0.0f);
            }
        }
    }
}

// =====================================================================
// Kernel 2: 3x3 conv (256->256, pad 1) + BN + ReLU.  [R9 winner]
// Column-half CTAs (equal work), E/O dual tile, TWO-PHASE over ic:
// tile holds 128 ics ([128][7r][10f] = 35KB) -> 4 CTA/SM, grid 512 =
// one fully-resident wave. No weight prefetch (TLP hides LDG latency).
// FMA order ic->dy->dx preserved (bit-exact). Measured 411.7us =
// 99.8% of the fp32 FMA-pipe roofline.
// =====================================================================
#define SM3_BYTES (128 * 70 * 4)

__global__ void __launch_bounds__(256, 4) k_conv3x3(
    const float* __restrict__ in, const ull* __restrict__ wt,
    const float* __restrict__ b, const float* __restrict__ g,
    const float* __restrict__ be, const float* __restrict__ mu,
    const float* __restrict__ var, float* __restrict__ out)
{
    extern __shared__ float sm[];
    const int blk = blockIdx.x;
    const int bidx = blk >> 1;
    const int half = blk & 1;
    const int tid = threadIdx.x;
    const float* inb = in + (size_t)bidx * 256 * 49;

    const int cw = half ? 4 : 5;       // valid cols to load
    const int coff = half ? 0 : 1;     // first valid tile col
    const int xoff = half ? 3 : 0;     // input x of first valid col

    for (int k = tid; k < 128 * 35; k += 256) ((ull*)sm)[k] = 0ull;

    const int oc = tid;
    ull acc[7][2];
#pragma unroll
    for (int y = 0; y < 7; y++) {
        acc[y][0] = 0ull;
        acc[y][1] = 0ull;
    }

    const int nload = 128 * 7 * cw;

#pragma unroll 1
    for (int ph = 0; ph < 2; ph++) {
        __syncthreads();   // prior-phase compute (or zeroing) done
        const float* inph = inb + ph * 128 * 49;
        for (int k = tid; k < nload; k += 256) {
            int icl = k / (7 * cw), rem = k % (7 * cw);
            int r = rem / cw, j = rem % cw;
            float v = inph[icl * 49 + r * 7 + xoff + j];
            int base = icl * 70 + r * 10;
            int cpos = coff + j;
            sm[base + cpos] = v;                                      // E: c0..c5
            if (cpos >= 1 && cpos <= 4) sm[base + 6 + (cpos - 1)] = v;   // O: c1..c4
        }
        __syncthreads();

        const ull* wtp = wt + (size_t)ph * 128 * 9 * 256 + oc;
#pragma unroll 1
        for (int icl = 0; icl < 128; icl++) {
            ull wc[9];
#pragma unroll
            for (int t = 0; t < 9; t++) wc[t] = __ldg(wtp + (icl * 9 + t) * 256);

            const ull* rowb = (const ull*)sm + icl * 35;
#pragma unroll
            for (int r = 0; r < 7; r++) {
                ull E0 = rowb[r * 5 + 0], E1 = rowb[r * 5 + 1], E2 = rowb[r * 5 + 2];
                ull O0 = rowb[r * 5 + 3], O1 = rowb[r * 5 + 4];
#pragma unroll
                for (int dy = 0; dy < 3; dy++) {
                    int yy = r - dy + 1;
                    if (yy < 0 || yy > 6) continue;
                    acc[yy][0] = fma2(wc[dy * 3 + 0], E0, acc[yy][0]);
                    acc[yy][0] = fma2(wc[dy * 3 + 1], O0, acc[yy][0]);
                    acc[yy][0] = fma2(wc[dy * 3 + 2], E1, acc[yy][0]);
                    acc[yy][1] = fma2(wc[dy * 3 + 0], E1, acc[yy][1]);
                    acc[yy][1] = fma2(wc[dy * 3 + 1], O1, acc[yy][1]);
                    acc[yy][1] = fma2(wc[dy * 3 + 2], E2, acc[yy][1]);
                }
            }
        }
    }

    float inv = g[oc] * rsqrtf(var[oc] + 1e-5f);
    float sh = (b[oc] - mu[oc]) * inv + be[oc];
    float* outp = out + (size_t)bidx * 256 * 49 + oc * 49;
    const int xbase = half ? 4 : 0;
#pragma unroll
    for (int yy = 0; yy < 7; yy++) {
#pragma unroll
        for (int k2 = 0; k2 < 2; k2++) {
            float vlo, vhi;
            unpack2(acc[yy][k2], vlo, vhi);
            int x = xbase + 2 * k2;
            outp[yy * 7 + x] = fmaxf(vlo * inv + sh, 0.0f);
            if (x + 1 < 7) outp[yy * 7 + x + 1] = fmaxf(vhi * inv + sh, 0.0f);
        }
    }
}

// =====================================================================
// Kernel 3: heads — 3x3 conv into 12 cls + 48 box channels (+bias).
// [R10 winner] Half-image CTAs by row, E/O dual-layout rows, TWO-PHASE
// over ic: tile [128 ic][6 rows][18 floats] = 54KB -> 4 CTA/SM,
// grid 512 = 1 wave. Same tap order as reference -> bit-exact.
// =====================================================================
#define SMH_BYTES (128 * 108 * 4)

__global__ void __launch_bounds__(256, 4) k_heads(
    const float* __restrict__ in, const ull* __restrict__ wt,
    const float* __restrict__ bcls, const float* __restrict__ bbox,
    float* __restrict__ boxpred, float* __restrict__ scores)
{
    extern __shared__ float sm[];
    const int blk = blockIdx.x;
    const int bidx = blk >> 1;
    const int half = blk & 1;
    const int tid = threadIdx.x;
    const float* inb = in + (size_t)bidx * 256 * 49;
    const int base = half ? 3 : -1;      // smem row r = input row base+r
    const int outbase = half ? 4 : 0;

    for (int k = tid; k < 128 * 54; k += 256) ((ull*)sm)[k] = 0ull;

    const int slot = tid & 63;
    const int lr = tid >> 6;      // 0..3
    const int yout = outbase + lr;
    const bool valid = (yout < 7);

    ull acc[4];
#pragma unroll
    for (int k2 = 0; k2 < 4; k2++) acc[k2] = 0ull;

#pragma unroll 1
    for (int ph = 0; ph < 2; ph++) {
        __syncthreads();
        const float* inph = inb + ph * 128 * 49;
        for (int k = tid; k < 128 * 42; k += 256) {
            int icl = k / 42, rem = k % 42, r = rem / 7, x = rem % 7;
            int y = base + r;
            if (y >= 0 && y <= 6) {
                float v = inph[icl * 49 + y * 7 + x];
                int rbase = icl * 108 + r * 18;
                sm[rbase + x + 1] = v;        // E slots
                sm[rbase + 10 + x] = v;       // O slots
            }
        }
        __syncthreads();

        if (valid) {
            const ull* wtp = wt + (size_t)ph * 128 * 9 * 64 + slot;
#pragma unroll 1
            for (int icl = 0; icl < 128; icl++) {
                ull wc[9];
#pragma unroll
                for (int t = 0; t < 9; t++) wc[t] = __ldg(wtp + (icl * 9 + t) * 64);

#pragma unroll
                for (int dy = 0; dy < 3; dy++) {
                    int r = lr + dy;
                    const ull* rp = (const ull*)(sm + icl * 108 + r * 18);
                    ull E0 = rp[0], E1 = rp[1], E2 = rp[2], E3 = rp[3], E4 = rp[4];
                    ull O0 = rp[5], O1 = rp[6], O2 = rp[7], O3 = rp[8];
                    acc[0] = fma2(wc[dy * 3 + 0], E0, acc[0]);
                    acc[0] = fma2(wc[dy * 3 + 1], O0, acc[0]);
                    acc[0] = fma2(wc[dy * 3 + 2], E1, acc[0]);
                    acc[1] = fma2(wc[dy * 3 + 0], E1, acc[1]);
                    acc[1] = fma2(wc[dy * 3 + 1], O1, acc[1]);
                    acc[1] = fma2(wc[dy * 3 + 2], E2, acc[1]);
                    acc[2] = fma2(wc[dy * 3 + 0], E2, acc[2]);
                    acc[2] = fma2(wc[dy * 3 + 1], O2, acc[2]);
                    acc[2] = fma2(wc[dy * 3 + 2], E3, acc[2]);
                    acc[3] = fma2(wc[dy * 3 + 0], E3, acc[3]);
                    acc[3] = fma2(wc[dy * 3 + 1], O3, acc[3]);
                    acc[3] = fma2(wc[dy * 3 + 2], E4, acc[3]);
                }
            }
        }
    }

    if (!valid) return;

    if (slot < 12) {
        float bv = bcls[slot];
#pragma unroll
        for (int k2 = 0; k2 < 4; k2++) {
            float vlo, vhi;
            unpack2(acc[k2], vlo, vhi);
            int x = 2 * k2;
            int p0 = yout * 7 + x;
            scores[(size_t)bidx * 588 + p0 * 12 + slot] = xla_sigmoid(vlo + bv);
            if (x + 1 < 7)
                scores[(size_t)bidx * 588 + (p0 + 1) * 12 + slot] = xla_sigmoid(vhi + bv);
        }
    } else if (slot < 60) {
        int c = slot - 12;
        int a = c >> 2, coord = c & 3;
        float bv = bbox[c];
#pragma unroll
        for (int k2 = 0; k2 < 4; k2++) {
            float vlo, vhi;
            unpack2(acc[k2], vlo, vhi);
            int x = 2 * k2;
            int p0 = yout * 7 + x;
            boxpred[((size_t)bidx * 588 + p0 * 12 + a) * 4 + coord] = vlo + bv;
            if (x + 1 < 7)
                boxpred[((size_t)bidx * 588 + (p0 + 1) * 12 + a) * 4 + coord] = vhi + bv;
        }
    }
}

// =====================================================================
// Kernel 4: decode + exact greedy NMS. One block (256 thr) per image.
// =====================================================================
#define SMN_BYTES (6468 * 4 + 588 * 8 + 588 * 19 * 4 + 101 * 4)

__global__ void __launch_bounds__(256) k_nms(
    const float* __restrict__ boxpred, const float* __restrict__ scores,
    float* __restrict__ out)
{
    extern __shared__ float sm[];
    float* dbx = sm;
    float* dsc = dbx + 2352;
    float* sbx = dsc + 588;
    float* ss = sbx + 2352;
    float* sar = ss + 588;
    ull* keys = (ull*)(sar + 588);
    unsigned* adj = (unsigned*)(keys + 588);
    int* keepL = (int*)(adj + 588 * 19);
    int* keepCnt = keepL + 100;

    const int bidx = blockIdx.x;
    const int tid = threadIdx.x;
    const float* bp = boxpred + (size_t)bidx * 588 * 4;
    const float* sc = scores + (size_t)bidx * 588;

    const float SCALES[4] = {0.3f, 0.5f, 0.7f, 0.9f};
    const float RATIOS[3] = {0.7f, 1.0f, 1.3f};

    for (int i = tid; i < 588; i += 256) {
        int p = i / 12, a = i % 12;
        int si = a / 3, ri = a % 3;
        float cx = ((float)(p / 7) + 0.5f) / 7.0f;
        float cy = ((float)(p % 7) + 0.5f) / 7.0f;
        float rt = sqrtf(RATIOS[ri]);
        float ws = SCALES[si] * rt;
        float hs = SCALES[si] / rt;
        float hw = ws * 0.5f, hh = hs * 0.5f;
        float a0 = cx - hw, a1 = cy - hh, a2 = cx + hw, a3 = cy + hh;
        float acx = (a0 + a2) * 0.5f, acy = (a1 + a3) * 0.5f;
        float aszx = a2 - a0, aszy = a3 - a1;
        float t0 = bp[i * 4 + 0], t1 = bp[i * 4 + 1];
        float t2 = bp[i * 4 + 2], t3 = bp[i * 4 + 3];
        float pcx = t0 * aszx + acx;
        float pcy = t1 * aszy + acy;
        float psx = expf(t2) * aszx;
        float psy = expf(t3) * aszy;
        dbx[i * 4 + 0] = pcx - psx * 0.5f;
        dbx[i * 4 + 1] = pcy - psy * 0.5f;
        dbx[i * 4 + 2] = pcx + psx * 0.5f;
        dbx[i * 4 + 3] = pcy + psy * 0.5f;
        float s = sc[i];
        dsc[i] = s;
        keys[i] = (((ull)(0xFFFFFFFFu - __float_as_uint(s))) << 32) | (unsigned)i;
    }
    __syncthreads();

    for (int i = tid; i < 588; i += 256) {
        ull ki = keys[i];
        int r = 0;
        for (int j = 0; j < 588; j++) r += (keys[j] < ki) ? 1 : 0;
        ss[r] = dsc[i];
        float x0 = dbx[i * 4 + 0], y0 = dbx[i * 4 + 1];
        float x1 = dbx[i * 4 + 2], y1 = dbx[i * 4 + 3];
        sbx[r * 4 + 0] = x0;
        sbx[r * 4 + 1] = y0;
        sbx[r * 4 + 2] = x1;
        sbx[r * 4 + 3] = y1;
        sar[r] = (x1 - x0) * (y1 - y0);
    }
    __syncthreads();

    for (int t = tid; t < 588 * 19; t += 256) {
        int i = t / 19, wdi = t % 19;
        unsigned word = 0;
        if (ss[i] > CONF_THR) {
            float ax0 = sbx[i * 4 + 0], ay0 = sbx[i * 4 + 1];
            float ax1 = sbx[i * 4 + 2], ay1 = sbx[i * 4 + 3];
            float aar = sar[i];
            int j0 = wdi * 32;
            int jend = min(588 - j0, 32);
            for (int bb = 0; bb < jend; bb++) {
                int j = j0 + bb;
                float lx = fmaxf(ax0, sbx[j * 4 + 0]);
                float ly = fmaxf(ay0, sbx[j * 4 + 1]);
                float rx = fminf(ax1, sbx[j * 4 + 2]);
                float ry = fminf(ay1, sbx[j * 4 + 3]);
                float iw = fmaxf(rx - lx, 0.0f);
                float ih = fmaxf(ry - ly, 0.0f);
                float inter = iw * ih;
                float iou = inter / (aar + sar[j] - inter + 1e-9f);
                if (iou > NMS_THRV) word |= (1u << bb);
            }
        }
        adj[i * 19 + wdi] = word;
    }
    __syncthreads();

    if (tid == 0) {
        unsigned sup[19];
#pragma unroll
        for (int w2 = 0; w2 < 19; w2++) sup[w2] = 0u;
        int cnt = 0;
        for (int i = 0; i < 588; i++) {
            if (!(ss[i] > CONF_THR)) break;
            if ((sup[i >> 5] >> (i & 31)) & 1u) continue;
            keepL[cnt++] = i;
            if (cnt == MAXDET) break;
            int w0 = i >> 5, bpos = i & 31;
            unsigned m0 = (bpos == 31) ? 0u : (0xFFFFFFFFu << (bpos + 1));
            sup[w0] |= adj[i * 19 + w0] & m0;
            for (int w2 = w0 + 1; w2 < 19; w2++) sup[w2] |= adj[i * 19 + w2];
        }
        *keepCnt = cnt;
    }
    __syncthreads();

    int cnt = *keepCnt;
    for (int r = tid; r < MAXDET; r += 256) {
        float* o = out + ((size_t)bidx * MAXDET + r) * 6;
        if (r < cnt) {
            int i = keepL[r];
            o[0] = sbx[i * 4 + 0];
            o[1] = sbx[i * 4 + 1];
            o[2] = sbx[i * 4 + 2];
            o[3] = sbx[i * 4 + 3];
            o[4] = ss[i];
            o[5] = 1.0f;
        } else {
            o[0] = 0.0f; o[1] = 0.0f; o[2] = 0.0f;
            o[3] = 0.0f; o[4] = 0.0f; o[5] = 0.0f;
        }
    }
}

// =====================================================================
// launcher
// =====================================================================
extern "C" void kernel_launch(void* const* d_in, const int* in_sizes, int n_in,
                              void* d_out, int out_size)
{
    (void)in_sizes; (void)n_in; (void)out_size;

    const float* features = (const float*)d_in[0];
    const float* w1 = (const float*)d_in[1];
    const float* b1 = (const float*)d_in[2];
    const float* g1 = (const float*)d_in[3];
    const float* be1 = (const float*)d_in[4];
    const float* mu1 = (const float*)d_in[5];
    const float* var1 = (const float*)d_in[6];
    const float* w2 = (const float*)d_in[7];
    const float* b2 = (const float*)d_in[8];
    const float* g2 = (const float*)d_in[9];
    const float* be2 = (const float*)d_in[10];
    const float* mu2 = (const float*)d_in[11];
    const float* var2 = (const float*)d_in[12];
    const float* w3 = (const float*)d_in[13];
    const float* b3 = (const float*)d_in[14];
    const float* g3 = (const float*)d_in[15];
    const float* be3 = (const float*)d_in[16];
    const float* mu3 = (const float*)d_in[17];
    const float* var3 = (const float*)d_in[18];
    const float* w4 = (const float*)d_in[19];
    const float* b4 = (const float*)d_in[20];
    const float* g4 = (const float*)d_in[21];
    const float* be4 = (const float*)d_in[22];
    const float* mu4 = (const float*)d_in[23];
    const float* var4 = (const float*)d_in[24];
    const float* w_cls = (const float*)d_in[25];
    const float* b_cls = (const float*)d_in[26];
    const float* w_box = (const float*)d_in[27];
    const float* b_box = (const float*)d_in[28];
    float* out = (float*)d_out;

    float *act0, *act1, *bpred, *scr;
    ull *wt1, *wt2, *wt3, *wt4, *wth;
    cudaGetSymbolAddress((void**)&act0, g_act0);
    cudaGetSymbolAddress((void**)&act1, g_act1);
    cudaGetSymbolAddress((void**)&bpred, g_boxpred);
    cudaGetSymbolAddress((void**)&scr, g_scores);
    cudaGetSymbolAddress((void**)&wt1, g_wt1);
    cudaGetSymbolAddress((void**)&wt2, g_wt2);
    cudaGetSymbolAddress((void**)&wt3, g_wt3);
    cudaGetSymbolAddress((void**)&wt4, g_wt4);
    cudaGetSymbolAddress((void**)&wth, g_wth);

    cudaFuncSetAttribute(k_conv1x1, cudaFuncAttributeMaxDynamicSharedMemorySize, SM1_BYTES);
    cudaFuncSetAttribute(k_conv3x3, cudaFuncAttributeMaxDynamicSharedMemorySize, SM3_BYTES);
    cudaFuncSetAttribute(k_heads, cudaFuncAttributeMaxDynamicSharedMemorySize, SMH_BYTES);
    cudaFuncSetAttribute(k_nms, cudaFuncAttributeMaxDynamicSharedMemorySize, SMN_BYTES);

    k_wt<<<(NT_TOTAL + 255) / 256, 256>>>(w1, w2, w3, w4, w_cls, w_box);
    k_conv1x1<<<512, 256, SM1_BYTES>>>(features, wt1, b1, g1, be1, mu1, var1, act0);
    k_conv3x3<<<512, 256, SM3_BYTES>>>(act0, wt2, b2, g2, be2, mu2, var2, act1);
    k_conv3x3<<<512, 256, SM3_BYTES>>>(act1, wt3, b3, g3, be3, mu3, var3, act0);
    k_conv3x3<<<512, 256, SM3_BYTES>>>(act0, wt4, b4, g4, be4, mu4, var4, act1);
    k_heads<<<512, 256, SMH_BYTES>>>(act1, wth, b_cls, b_box, bpred, scr);
    k_nms<<<256, 256, SMN_BYTES>>>(bpred, scr, out);
}

// round 12
// speedup vs baseline: 1.0486x; 1.0251x over previous
#include <cuda_runtime.h>
#include <math.h>

typedef unsigned long long ull;

#define CONF_THR 0.3f
#define NMS_THRV 0.5f
#define MAXDET 100

// ---------------- scratch (static device arrays; no allocation) ----------------
__device__ float g_act0[256 * 256 * 49];
__device__ float g_act1[256 * 256 * 49];
__device__ float g_boxpred[256 * 588 * 4];
__device__ float g_scores[256 * 588];
// transposed, pair-duplicated {w,w} u64 weights (padded)
__device__ ull g_wt1[512 * 256 + 256];
__device__ ull g_wt2[2304 * 256 + 2560];
__device__ ull g_wt3[2304 * 256 + 2560];
__device__ ull g_wt4[2304 * 256 + 2560];
__device__ ull g_wth[2304 * 64 + 640];

// ---------------- packed f32x2 helpers ----------------
__device__ __forceinline__ ull fma2(ull a, ull b, ull c) {
    ull d;
    asm("fma.rn.f32x2 %0, %1, %2, %3;" : "=l"(d) : "l"(a), "l"(b), "l"(c));
    return d;
}
__device__ __forceinline__ ull pack2(float lo, float hi) {
    unsigned l = __float_as_uint(lo), h = __float_as_uint(hi);
    ull d;
    asm("mov.b64 %0, {%1, %2};" : "=l"(d) : "r"(l), "r"(h));
    return d;
}
__device__ __forceinline__ void unpack2(ull v, float& lo, float& hi) {
    unsigned l, h;
    asm("mov.b64 {%0, %1}, %2;" : "=r"(l), "=r"(h) : "l"(v));
    lo = __uint_as_float(l);
    hi = __uint_as_float(h);
}
__device__ __forceinline__ float lo32f(ull v) { return __uint_as_float((unsigned)v); }
__device__ __forceinline__ float hi32f(ull v) { return __uint_as_float((unsigned)(v >> 32)); }

// ---------------- XLA logistic: 0.5 + 0.5*tanh(0.5*x), XLA fast-tanh f32 ----------------
__device__ __forceinline__ float xla_tanh(float x) {
    float ax = fabsf(x);
    float xc = fminf(fmaxf(x, -9.0f), 9.0f);
    float x2 = xc * xc;
    float p = fmaf(x2, -2.76076847742355e-16f, 2.00018790482477e-13f);
    p = fmaf(x2, p, -8.60467152213735e-11f);
    p = fmaf(x2, p, 5.12229709037114e-08f);
    p = fmaf(x2, p, 1.48572235717979e-05f);
    p = fmaf(x2, p, 6.37261928875436e-04f);
    p = fmaf(x2, p, 4.89352455891786e-03f);
    p = xc * p;
    float q = fmaf(x2, 1.19825839466702e-06f, 1.18534705686654e-04f);
    q = fmaf(x2, q, 2.26843463243900e-03f);
    q = fmaf(x2, q, 4.89352518554385e-03f);
    float r = p / q;
    return (ax < 0.0004f) ? x : r;
}
__device__ __forceinline__ float xla_sigmoid(float x) {
    float t = xla_tanh(0.5f * x);
    return 0.5f + 0.5f * t;
}

// =====================================================================
// Kernel 0: weight transpose + {w,w} duplication.
// =====================================================================
#define NT1 (512 * 256)
#define NT3 (2304 * 256)
#define NTH (2304 * 64)
#define NT_TOTAL (NT1 + 3 * NT3 + NTH)

__global__ void __launch_bounds__(256) k_wt(
    const float* __restrict__ w1, const float* __restrict__ w2,
    const float* __restrict__ w3, const float* __restrict__ w4,
    const float* __restrict__ wcls, const float* __restrict__ wbox)
{
    int idx = blockIdx.x * 256 + threadIdx.x;
    if (idx < NT1) {
        int oc = idx & 255, ic = idx >> 8;
        float v = w1[oc * 512 + ic];
        g_wt1[idx] = pack2(v, v);
        return;
    }
    idx -= NT1;
    if (idx < NT3) {
        int oc = idx & 255, k = idx >> 8;
        float v = w2[oc * 2304 + k];
        g_wt2[idx] = pack2(v, v);
        return;
    }
    idx -= NT3;
    if (idx < NT3) {
        int oc = idx & 255, k = idx >> 8;
        float v = w3[oc * 2304 + k];
        g_wt3[idx] = pack2(v, v);
        return;
    }
    idx -= NT3;
    if (idx < NT3) {
        int oc = idx & 255, k = idx >> 8;
        float v = w4[oc * 2304 + k];
        g_wt4[idx] = pack2(v, v);
        return;
    }
    idx -= NT3;
    if (idx < NTH) {
        int slot = idx & 63, k = idx >> 6;
        float v = 0.0f;
        if (slot < 12) v = wcls[slot * 2304 + k];
        else if (slot < 60) v = wbox[(slot - 12) * 2304 + k];
        g_wth[idx] = pack2(v, v);
    }
}

// =====================================================================
// Kernel 1: 1x1 conv (512->256) + BN + ReLU.
// Half-image CTAs by position. smem [512][26] (53.2KB) -> 4 CTA/SM.
// 256 threads: ocpair = tid&127, sub = tid>>7. Writes clamped to half.
// =====================================================================
#define SM1_BYTES (512 * 26 * 4)

__global__ void __launch_bounds__(256, 4) k_conv1x1(
    const float* __restrict__ in, const ull* __restrict__ wt,
    const float* __restrict__ b, const float* __restrict__ g,
    const float* __restrict__ be, const float* __restrict__ mu,
    const float* __restrict__ var, float* __restrict__ out)
{
    extern __shared__ float sm[];
    const int blk = blockIdx.x;
    const int bidx = blk >> 1;
    const int half = blk & 1;
    const int tid = threadIdx.x;
    const float* inb = in + (size_t)bidx * 512 * 49;
    const int p0 = half ? 24 : 0;
    const int np = half ? 25 : 24;
    const int plimit = p0 + np;

    for (int k = tid; k < 512 * 13; k += 256) ((ull*)sm)[k] = 0ull;
    __syncthreads();
    for (int k = tid; k < 512 * np; k += 256) {
        int ic = k / np, p = k % np;
        sm[ic * 26 + p] = inb[ic * 49 + p0 + p];
    }
    __syncthreads();

    const int op = tid & 127;
    const int sub = tid >> 7;
    const int oc0 = op * 2;
    const int pp0 = sub ? 7 : 0;
    const int pn = sub ? 6 : 7;

    ull acc[2][7];
#pragma unroll
    for (int j = 0; j < 2; j++)
#pragma unroll
        for (int p = 0; p < 7; p++) acc[j][p] = 0ull;

#pragma unroll 1
    for (int ic = 0; ic < 512; ic++) {
        ulonglong2 wv = *(const ulonglong2*)(wt + ic * 256 + oc0);
        const ull* row = (const ull*)(sm + ic * 26) + pp0;
#pragma unroll
        for (int p = 0; p < 7; p++) {
            if (sub == 0 || p < 6) {
                ull x = row[p];
                acc[0][p] = fma2(wv.x, x, acc[0][p]);
                acc[1][p] = fma2(wv.y, x, acc[1][p]);
            }
        }
    }

#pragma unroll
    for (int j = 0; j < 2; j++) {
        int oc = oc0 + j;
        float inv = g[oc] * rsqrtf(var[oc] + 1e-5f);
        float sh = (b[oc] - mu[oc]) * inv + be[oc];
        float* outp = out + (size_t)bidx * 256 * 49 + oc * 49;
#pragma unroll
        for (int p = 0; p < 7; p++) {
            if (p < pn) {
                float vlo, vhi;
                unpack2(acc[j][p], vlo, vhi);
                int pos = p0 + 2 * (pp0 + p);
                if (pos < plimit) outp[pos] = fmaxf(vlo * inv + sh, 0.0f);
                if (pos + 1 < plimit) outp[pos + 1] = fmaxf(vhi * inv + sh, 0.0f);
            }
        }
    }
}

// =====================================================================
// Kernel 2: 3x3 conv (256->256, pad 1) + BN + ReLU.
// Column-half CTAs, E/O dual tile, TWO-PHASE over ic (tile 35KB ->
// 4 CTA/SM, grid 512 = one wave).
// NEW: half1 computes pair (4,5) as FFMA2 + column 6 as scalar FFMA
// (rt 2 vs 4) -> no padded-column flops. Per-SM fma-pipe work -12.5%.
// FMA order ic->dy->dx preserved, zero-pad products included (bit-exact).
// =====================================================================
#define SM3_BYTES (128 * 70 * 4)

__global__ void __launch_bounds__(256, 4) k_conv3x3(
    const float* __restrict__ in, const ull* __restrict__ wt,
    const float* __restrict__ b, const float* __restrict__ g,
    const float* __restrict__ be, const float* __restrict__ mu,
    const float* __restrict__ var, float* __restrict__ out)
{
    extern __shared__ float sm[];
    const int blk = blockIdx.x;
    const int bidx = blk >> 1;
    const int half = blk & 1;
    const int tid = threadIdx.x;
    const float* inb = in + (size_t)bidx * 256 * 49;

    const int cw = half ? 4 : 5;       // valid cols to load
    const int coff = half ? 0 : 1;     // first valid tile col
    const int xoff = half ? 3 : 0;     // input x of first valid col

    for (int k = tid; k < 128 * 35; k += 256) ((ull*)sm)[k] = 0ull;

    const int oc = tid;
    ull acc[7][2];
    float accS[7];
#pragma unroll
    for (int y = 0; y < 7; y++) {
        acc[y][0] = 0ull;
        acc[y][1] = 0ull;
        accS[y] = 0.0f;
    }

    const int nload = 128 * 7 * cw;

#pragma unroll 1
    for (int ph = 0; ph < 2; ph++) {
        __syncthreads();   // prior-phase compute (or zeroing) done
        const float* inph = inb + ph * 128 * 49;
        for (int k = tid; k < nload; k += 256) {
            int icl = k / (7 * cw), rem = k % (7 * cw);
            int r = rem / cw, j = rem % cw;
            float v = inph[icl * 49 + r * 7 + xoff + j];
            int base = icl * 70 + r * 10;
            int cpos = coff + j;
            sm[base + cpos] = v;                                      // E: c0..c5
            if (cpos >= 1 && cpos <= 4) sm[base + 6 + (cpos - 1)] = v;   // O: c1..c4
        }
        __syncthreads();

        const ull* wtp = wt + (size_t)ph * 128 * 9 * 256 + oc;
        if (half == 0) {
            // out x0..3: two f32x2 pairs
#pragma unroll 1
            for (int icl = 0; icl < 128; icl++) {
                ull wc[9];
#pragma unroll
                for (int t = 0; t < 9; t++) wc[t] = __ldg(wtp + (icl * 9 + t) * 256);

                const ull* rowb = (const ull*)sm + icl * 35;
#pragma unroll
                for (int r = 0; r < 7; r++) {
                    ull E0 = rowb[r * 5 + 0], E1 = rowb[r * 5 + 1], E2 = rowb[r * 5 + 2];
                    ull O0 = rowb[r * 5 + 3], O1 = rowb[r * 5 + 4];
#pragma unroll
                    for (int dy = 0; dy < 3; dy++) {
                        int yy = r - dy + 1;
                        if (yy < 0 || yy > 6) continue;
                        acc[yy][0] = fma2(wc[dy * 3 + 0], E0, acc[yy][0]);
                        acc[yy][0] = fma2(wc[dy * 3 + 1], O0, acc[yy][0]);
                        acc[yy][0] = fma2(wc[dy * 3 + 2], E1, acc[yy][0]);
                        acc[yy][1] = fma2(wc[dy * 3 + 0], E1, acc[yy][1]);
                        acc[yy][1] = fma2(wc[dy * 3 + 1], O1, acc[yy][1]);
                        acc[yy][1] = fma2(wc[dy * 3 + 2], E2, acc[yy][1]);
                    }
                }
            }
        } else {
            // out x4,5 as pair + x6 scalar.
            // tile: c0..c3 = x3..x6. E0=(x3,x4) O0=(x4,x5) E1=(x5,x6).
            // pair (4,5): taps E0,O0,E1. scalar 6: taps x5(E1.lo), x6(E1.hi), x7=0.
#pragma unroll 1
            for (int icl = 0; icl < 128; icl++) {
                ull wc[9];
#pragma unroll
                for (int t = 0; t < 9; t++) wc[t] = __ldg(wtp + (icl * 9 + t) * 256);

                const ull* rowb = (const ull*)sm + icl * 35;
#pragma unroll
                for (int r = 0; r < 7; r++) {
                    ull E0 = rowb[r * 5 + 0], E1 = rowb[r * 5 + 1];
                    ull O0 = rowb[r * 5 + 3];
                    float x5 = lo32f(E1), x6 = hi32f(E1);
#pragma unroll
                    for (int dy = 0; dy < 3; dy++) {
                        int yy = r - dy + 1;
                        if (yy < 0 || yy > 6) continue;
                        acc[yy][0] = fma2(wc[dy * 3 + 0], E0, acc[yy][0]);
                        acc[yy][0] = fma2(wc[dy * 3 + 1], O0, acc[yy][0]);
                        acc[yy][0] = fma2(wc[dy * 3 + 2], E1, acc[yy][0]);
                        accS[yy] = fmaf(lo32f(wc[dy * 3 + 0]), x5, accS[yy]);
                        accS[yy] = fmaf(lo32f(wc[dy * 3 + 1]), x6, accS[yy]);
                        accS[yy] = fmaf(lo32f(wc[dy * 3 + 2]), 0.0f, accS[yy]);
                    }
                }
            }
        }
    }

    float inv = g[oc] * rsqrtf(var[oc] + 1e-5f);
    float sh = (b[oc] - mu[oc]) * inv + be[oc];
    float* outp = out + (size_t)bidx * 256 * 49 + oc * 49;
    if (half == 0) {
#pragma unroll
        for (int yy = 0; yy < 7; yy++) {
            float vlo, vhi;
            unpack2(acc[yy][0], vlo, vhi);
            outp[yy * 7 + 0] = fmaxf(vlo * inv + sh, 0.0f);
            outp[yy * 7 + 1] = fmaxf(vhi * inv + sh, 0.0f);
            unpack2(acc[yy][1], vlo, vhi);
            outp[yy * 7 + 2] = fmaxf(vlo * inv + sh, 0.0f);
            outp[yy * 7 + 3] = fmaxf(vhi * inv + sh, 0.0f);
        }
    } else {
#pragma unroll
        for (int yy = 0; yy < 7; yy++) {
            float vlo, vhi;
            unpack2(acc[yy][0], vlo, vhi);
            outp[yy * 7 + 4] = fmaxf(vlo * inv + sh, 0.0f);
            outp[yy * 7 + 5] = fmaxf(vhi * inv + sh, 0.0f);
            outp[yy * 7 + 6] = fmaxf(accS[yy] * inv + sh, 0.0f);
        }
    }
}

// =====================================================================
// Kernel 3: heads — 3x3 conv into 12 cls + 48 box channels (+bias).
// Half-image CTAs by row, E/O dual-layout rows, TWO-PHASE over ic:
// tile [128 ic][6 rows][18 floats] = 54KB -> 4 CTA/SM, grid 512 = 1 wave.
// NEW: 3 f32x2 pairs (x0..5) + scalar FFMA for x6 (drops padded x7 pair).
// Same tap order as reference -> bit-exact.
// =====================================================================
#define SMH_BYTES (128 * 108 * 4)

__global__ void __launch_bounds__(256, 4) k_heads(
    const float* __restrict__ in, const ull* __restrict__ wt,
    const float* __restrict__ bcls, const float* __restrict__ bbox,
    float* __restrict__ boxpred, float* __restrict__ scores)
{
    extern __shared__ float sm[];
    const int blk = blockIdx.x;
    const int bidx = blk >> 1;
    const int half = blk & 1;
    const int tid = threadIdx.x;
    const float* inb = in + (size_t)bidx * 256 * 49;
    const int base = half ? 3 : -1;      // smem row r = input row base+r
    const int outbase = half ? 4 : 0;

    for (int k = tid; k < 128 * 54; k += 256) ((ull*)sm)[k] = 0ull;

    const int slot = tid & 63;
    const int lr = tid >> 6;      // 0..3
    const int yout = outbase + lr;
    const bool valid = (yout < 7);

    ull acc[3];
    float accS = 0.0f;
#pragma unroll
    for (int k2 = 0; k2 < 3; k2++) acc[k2] = 0ull;

#pragma unroll 1
    for (int ph = 0; ph < 2; ph++) {
        __syncthreads();
        const float* inph = inb + ph * 128 * 49;
        for (int k = tid; k < 128 * 42; k += 256) {
            int icl = k / 42, rem = k % 42, r = rem / 7, x = rem % 7;
            int y = base + r;
            if (y >= 0 && y <= 6) {
                float v = inph[icl * 49 + y * 7 + x];
                int rbase = icl * 108 + r * 18;
                sm[rbase + x + 1] = v;        // E slots (value x at offset x+1)
                sm[rbase + 10 + x] = v;       // O slots (value x at offset 10+x)
            }
        }
        __syncthreads();

        if (valid) {
            const ull* wtp = wt + (size_t)ph * 128 * 9 * 64 + slot;
#pragma unroll 1
            for (int icl = 0; icl < 128; icl++) {
                ull wc[9];
#pragma unroll
                for (int t = 0; t < 9; t++) wc[t] = __ldg(wtp + (icl * 9 + t) * 64);

#pragma unroll
                for (int dy = 0; dy < 3; dy++) {
                    int r = lr + dy;
                    const ull* rp = (const ull*)(sm + icl * 108 + r * 18);
                    ull E0 = rp[0], E1 = rp[1], E2 = rp[2], E3 = rp[3];
                    ull O0 = rp[5], O1 = rp[6], O2 = rp[7];
                    float x5 = lo32f(E3), x6 = hi32f(E3);
                    acc[0] = fma2(wc[dy * 3 + 0], E0, acc[0]);
                    acc[0] = fma2(wc[dy * 3 + 1], O0, acc[0]);
                    acc[0] = fma2(wc[dy * 3 + 2], E1, acc[0]);
                    acc[1] = fma2(wc[dy * 3 + 0], E1, acc[1]);
                    acc[1] = fma2(wc[dy * 3 + 1], O1, acc[1]);
                    acc[1] = fma2(wc[dy * 3 + 2], E2, acc[1]);
                    acc[2] = fma2(wc[dy * 3 + 0], E2, acc[2]);
                    acc[2] = fma2(wc[dy * 3 + 1], O2, acc[2]);
                    acc[2] = fma2(wc[dy * 3 + 2], E3, acc[2]);
                    accS = fmaf(lo32f(wc[dy * 3 + 0]), x5, accS);
                    accS = fmaf(lo32f(wc[dy * 3 + 1]), x6, accS);
                    accS = fmaf(lo32f(wc[dy * 3 + 2]), 0.0f, accS);
                }
            }
        }
    }

    if (!valid) return;

    if (slot < 12) {
        float bv = bcls[slot];
#pragma unroll
        for (int k2 = 0; k2 < 3; k2++) {
            float vlo, vhi;
            unpack2(acc[k2], vlo, vhi);
            int x = 2 * k2;
            int p0 = yout * 7 + x;
            scores[(size_t)bidx * 588 + p0 * 12 + slot] = xla_sigmoid(vlo + bv);
            scores[(size_t)bidx * 588 + (p0 + 1) * 12 + slot] = xla_sigmoid(vhi + bv);
        }
        scores[(size_t)bidx * 588 + (yout * 7 + 6) * 12 + slot] = xla_sigmoid(accS + bv);
    } else if (slot < 60) {
        int c = slot - 12;
        int a = c >> 2, coord = c & 3;
        float bv = bbox[c];
#pragma unroll
        for (int k2 = 0; k2 < 3; k2++) {
            float vlo, vhi;
            unpack2(acc[k2], vlo, vhi);
            int x = 2 * k2;
            int p0 = yout * 7 + x;
            boxpred[((size_t)bidx * 588 + p0 * 12 + a) * 4 + coord] = vlo + bv;
            boxpred[((size_t)bidx * 588 + (p0 + 1) * 12 + a) * 4 + coord] = vhi + bv;
        }
        boxpred[((size_t)bidx * 588 + (yout * 7 + 6) * 12 + a) * 4 + coord] = accS + bv;
    }
}

// =====================================================================
// Kernel 4: decode + exact greedy NMS. One block (256 thr) per image.
// =====================================================================
#define SMN_BYTES (6468 * 4 + 588 * 8 + 588 * 19 * 4 + 101 * 4)

__global__ void __launch_bounds__(256) k_nms(
    const float* __restrict__ boxpred, const float* __restrict__ scores,
    float* __restrict__ out)
{
    extern __shared__ float sm[];
    float* dbx = sm;
    float* dsc = dbx + 2352;
    float* sbx = dsc + 588;
    float* ss = sbx + 2352;
    float* sar = ss + 588;
    ull* keys = (ull*)(sar + 588);
    unsigned* adj = (unsigned*)(keys + 588);
    int* keepL = (int*)(adj + 588 * 19);
    int* keepCnt = keepL + 100;

    const int bidx = blockIdx.x;
    const int tid = threadIdx.x;
    const float* bp = boxpred + (size_t)bidx * 588 * 4;
    const float* sc = scores + (size_t)bidx * 588;

    const float SCALES[4] = {0.3f, 0.5f, 0.7f, 0.9f};
    const float RATIOS[3] = {0.7f, 1.0f, 1.3f};

    for (int i = tid; i < 588; i += 256) {
        int p = i / 12, a = i % 12;
        int si = a / 3, ri = a % 3;
        float cx = ((float)(p / 7) + 0.5f) / 7.0f;
        float cy = ((float)(p % 7) + 0.5f) / 7.0f;
        float rt = sqrtf(RATIOS[ri]);
        float ws = SCALES[si] * rt;
        float hs = SCALES[si] / rt;
        float hw = ws * 0.5f, hh = hs * 0.5f;
        float a0 = cx - hw, a1 = cy - hh, a2 = cx + hw, a3 = cy + hh;
        float acx = (a0 + a2) * 0.5f, acy = (a1 + a3) * 0.5f;
        float aszx = a2 - a0, aszy = a3 - a1;
        float t0 = bp[i * 4 + 0], t1 = bp[i * 4 + 1];
        float t2 = bp[i * 4 + 2], t3 = bp[i * 4 + 3];
        float pcx = t0 * aszx + acx;
        float pcy = t1 * aszy + acy;
        float psx = expf(t2) * aszx;
        float psy = expf(t3) * aszy;
        dbx[i * 4 + 0] = pcx - psx * 0.5f;
        dbx[i * 4 + 1] = pcy - psy * 0.5f;
        dbx[i * 4 + 2] = pcx + psx * 0.5f;
        dbx[i * 4 + 3] = pcy + psy * 0.5f;
        float s = sc[i];
        dsc[i] = s;
        keys[i] = (((ull)(0xFFFFFFFFu - __float_as_uint(s))) << 32) | (unsigned)i;
    }
    __syncthreads();

    for (int i = tid; i < 588; i += 256) {
        ull ki = keys[i];
        int r = 0;
        for (int j = 0; j < 588; j++) r += (keys[j] < ki) ? 1 : 0;
        ss[r] = dsc[i];
        float x0 = dbx[i * 4 + 0], y0 = dbx[i * 4 + 1];
        float x1 = dbx[i * 4 + 2], y1 = dbx[i * 4 + 3];
        sbx[r * 4 + 0] = x0;
        sbx[r * 4 + 1] = y0;
        sbx[r * 4 + 2] = x1;
        sbx[r * 4 + 3] = y1;
        sar[r] = (x1 - x0) * (y1 - y0);
    }
    __syncthreads();

    for (int t = tid; t < 588 * 19; t += 256) {
        int i = t / 19, wdi = t % 19;
        unsigned word = 0;
        if (ss[i] > CONF_THR) {
            float ax0 = sbx[i * 4 + 0], ay0 = sbx[i * 4 + 1];
            float ax1 = sbx[i * 4 + 2], ay1 = sbx[i * 4 + 3];
            float aar = sar[i];
            int j0 = wdi * 32;
            int jend = min(588 - j0, 32);
            for (int bb = 0; bb < jend; bb++) {
                int j = j0 + bb;
                float lx = fmaxf(ax0, sbx[j * 4 + 0]);
                float ly = fmaxf(ay0, sbx[j * 4 + 1]);
                float rx = fminf(ax1, sbx[j * 4 + 2]);
                float ry = fminf(ay1, sbx[j * 4 + 3]);
                float iw = fmaxf(rx - lx, 0.0f);
                float ih = fmaxf(ry - ly, 0.0f);
                float inter = iw * ih;
                float iou = inter / (aar + sar[j] - inter + 1e-9f);
                if (iou > NMS_THRV) word |= (1u << bb);
            }
        }
        adj[i * 19 + wdi] = word;
    }
    __syncthreads();

    if (tid == 0) {
        unsigned sup[19];
#pragma unroll
        for (int w2 = 0; w2 < 19; w2++) sup[w2] = 0u;
        int cnt = 0;
        for (int i = 0; i < 588; i++) {
            if (!(ss[i] > CONF_THR)) break;
            if ((sup[i >> 5] >> (i & 31)) & 1u) continue;
            keepL[cnt++] = i;
            if (cnt == MAXDET) break;
            int w0 = i >> 5, bpos = i & 31;
            unsigned m0 = (bpos == 31) ? 0u : (0xFFFFFFFFu << (bpos + 1));
            sup[w0] |= adj[i * 19 + w0] & m0;
            for (int w2 = w0 + 1; w2 < 19; w2++) sup[w2] |= adj[i * 19 + w2];
        }
        *keepCnt = cnt;
    }
    __syncthreads();

    int cnt = *keepCnt;
    for (int r = tid; r < MAXDET; r += 256) {
        float* o = out + ((size_t)bidx * MAXDET + r) * 6;
        if (r < cnt) {
            int i = keepL[r];
            o[0] = sbx[i * 4 + 0];
            o[1] = sbx[i * 4 + 1];
            o[2] = sbx[i * 4 + 2];
            o[3] = sbx[i * 4 + 3];
            o[4] = ss[i];
            o[5] = 1.0f;
        } else {
            o[0] = 0.0f; o[1] = 0.0f; o[2] = 0.0f;
            o[3] = 0.0f; o[4] = 0.0f; o[5] = 0.0f;
        }
    }
}

// =====================================================================
// launcher
// =====================================================================
extern "C" void kernel_launch(void* const* d_in, const int* in_sizes, int n_in,
                              void* d_out, int out_size)
{
    (void)in_sizes; (void)n_in; (void)out_size;

    const float* features = (const float*)d_in[0];
    const float* w1 = (const float*)d_in[1];
    const float* b1 = (const float*)d_in[2];
    const float* g1 = (const float*)d_in[3];
    const float* be1 = (const float*)d_in[4];
    const float* mu1 = (const float*)d_in[5];
    const float* var1 = (const float*)d_in[6];
    const float* w2 = (const float*)d_in[7];
    const float* b2 = (const float*)d_in[8];
    const float* g2 = (const float*)d_in[9];
    const float* be2 = (const float*)d_in[10];
    const float* mu2 = (const float*)d_in[11];
    const float* var2 = (const float*)d_in[12];
    const float* w3 = (const float*)d_in[13];
    const float* b3 = (const float*)d_in[14];
    const float* g3 = (const float*)d_in[15];
    const float* be3 = (const float*)d_in[16];
    const float* mu3 = (const float*)d_in[17];
    const float* var3 = (const float*)d_in[18];
    const float* w4 = (const float*)d_in[19];
    const float* b4 = (const float*)d_in[20];
    const float* g4 = (const float*)d_in[21];
    const float* be4 = (const float*)d_in[22];
    const float* mu4 = (const float*)d_in[23];
    const float* var4 = (const float*)d_in[24];
    const float* w_cls = (const float*)d_in[25];
    const float* b_cls = (const float*)d_in[26];
    const float* w_box = (const float*)d_in[27];
    const float* b_box = (const float*)d_in[28];
    float* out = (float*)d_out;

    float *act0, *act1, *bpred, *scr;
    ull *wt1, *wt2, *wt3, *wt4, *wth;
    cudaGetSymbolAddress((void**)&act0, g_act0);
    cudaGetSymbolAddress((void**)&act1, g_act1);
    cudaGetSymbolAddress((void**)&bpred, g_boxpred);
    cudaGetSymbolAddress((void**)&scr, g_scores);
    cudaGetSymbolAddress((void**)&wt1, g_wt1);
    cudaGetSymbolAddress((void**)&wt2, g_wt2);
    cudaGetSymbolAddress((void**)&wt3, g_wt3);
    cudaGetSymbolAddress((void**)&wt4, g_wt4);
    cudaGetSymbolAddress((void**)&wth, g_wth);

    cudaFuncSetAttribute(k_conv1x1, cudaFuncAttributeMaxDynamicSharedMemorySize, SM1_BYTES);
    cudaFuncSetAttribute(k_conv3x3, cudaFuncAttributeMaxDynamicSharedMemorySize, SM3_BYTES);
    cudaFuncSetAttribute(k_heads, cudaFuncAttributeMaxDynamicSharedMemorySize, SMH_BYTES);
    cudaFuncSetAttribute(k_nms, cudaFuncAttributeMaxDynamicSharedMemorySize, SMN_BYTES);

    k_wt<<<(NT_TOTAL + 255) / 256, 256>>>(w1, w2, w3, w4, w_cls, w_box);
    k_conv1x1<<<512, 256, SM1_BYTES>>>(features, wt1, b1, g1, be1, mu1, var1, act0);
    k_conv3x3<<<512, 256, SM3_BYTES>>>(act0, wt2, b2, g2, be2, mu2, var2, act1);
    k_conv3x3<<<512, 256, SM3_BYTES>>>(act1, wt3, b3, g3, be3, mu3, var3, act0);
    k_conv3x3<<<512, 256, SM3_BYTES>>>(act0, wt4, b4, g4, be4, mu4, var4, act1);
    k_heads<<<512, 256, SMH_BYTES>>>(act1, wth, b_cls, b_box, bpred, scr);
    k_nms<<<256, 256, SMN_BYTES>>>(bpred, scr, out);
}

// round 13
// speedup vs baseline: 1.0746x; 1.0248x over previous
#include <cuda_runtime.h>
#include <math.h>

typedef unsigned long long ull;

#define CONF_THR 0.3f
#define NMS_THRV 0.5f
#define MAXDET 100

// ---------------- scratch (static device arrays; no allocation) ----------------
__device__ float g_act0[256 * 256 * 49];
__device__ float g_act1[256 * 256 * 49];
__device__ float g_boxpred[256 * 588 * 4];
__device__ float g_scores[256 * 588];
// transposed, pair-duplicated {w,w} u64 weights (padded)
__device__ ull g_wt1[512 * 256 + 256];
__device__ ull g_wt2[2304 * 256 + 2560];
__device__ ull g_wt3[2304 * 256 + 2560];
__device__ ull g_wt4[2304 * 256 + 2560];
__device__ ull g_wth[2304 * 64 + 640];

// ---------------- packed f32x2 helpers ----------------
__device__ __forceinline__ ull fma2(ull a, ull b, ull c) {
    ull d;
    asm("fma.rn.f32x2 %0, %1, %2, %3;" : "=l"(d) : "l"(a), "l"(b), "l"(c));
    return d;
}
__device__ __forceinline__ ull pack2(float lo, float hi) {
    unsigned l = __float_as_uint(lo), h = __float_as_uint(hi);
    ull d;
    asm("mov.b64 %0, {%1, %2};" : "=l"(d) : "r"(l), "r"(h));
    return d;
}
__device__ __forceinline__ void unpack2(ull v, float& lo, float& hi) {
    unsigned l, h;
    asm("mov.b64 {%0, %1}, %2;" : "=r"(l), "=r"(h) : "l"(v));
    lo = __uint_as_float(l);
    hi = __uint_as_float(h);
}
__device__ __forceinline__ float lo32f(ull v) { return __uint_as_float((unsigned)v); }
__device__ __forceinline__ float hi32f(ull v) { return __uint_as_float((unsigned)(v >> 32)); }

// ---------------- XLA logistic: 0.5 + 0.5*tanh(0.5*x), XLA fast-tanh f32 ----------------
__device__ __forceinline__ float xla_tanh(float x) {
    float ax = fabsf(x);
    float xc = fminf(fmaxf(x, -9.0f), 9.0f);
    float x2 = xc * xc;
    float p = fmaf(x2, -2.76076847742355e-16f, 2.00018790482477e-13f);
    p = fmaf(x2, p, -8.60467152213735e-11f);
    p = fmaf(x2, p, 5.12229709037114e-08f);
    p = fmaf(x2, p, 1.48572235717979e-05f);
    p = fmaf(x2, p, 6.37261928875436e-04f);
    p = fmaf(x2, p, 4.89352455891786e-03f);
    p = xc * p;
    float q = fmaf(x2, 1.19825839466702e-06f, 1.18534705686654e-04f);
    q = fmaf(x2, q, 2.26843463243900e-03f);
    q = fmaf(x2, q, 4.89352518554385e-03f);
    float r = p / q;
    return (ax < 0.0004f) ? x : r;
}
__device__ __forceinline__ float xla_sigmoid(float x) {
    float t = xla_tanh(0.5f * x);
    return 0.5f + 0.5f * t;
}

// =====================================================================
// Kernel 0: weight transpose + {w,w} duplication.
// =====================================================================
#define NT1 (512 * 256)
#define NT3 (2304 * 256)
#define NTH (2304 * 64)
#define NT_TOTAL (NT1 + 3 * NT3 + NTH)

__global__ void __launch_bounds__(256) k_wt(
    const float* __restrict__ w1, const float* __restrict__ w2,
    const float* __restrict__ w3, const float* __restrict__ w4,
    const float* __restrict__ wcls, const float* __restrict__ wbox)
{
    int idx = blockIdx.x * 256 + threadIdx.x;
    if (idx < NT1) {
        int oc = idx & 255, ic = idx >> 8;
        float v = w1[oc * 512 + ic];
        g_wt1[idx] = pack2(v, v);
        return;
    }
    idx -= NT1;
    if (idx < NT3) {
        int oc = idx & 255, k = idx >> 8;
        float v = w2[oc * 2304 + k];
        g_wt2[idx] = pack2(v, v);
        return;
    }
    idx -= NT3;
    if (idx < NT3) {
        int oc = idx & 255, k = idx >> 8;
        float v = w3[oc * 2304 + k];
        g_wt3[idx] = pack2(v, v);
        return;
    }
    idx -= NT3;
    if (idx < NT3) {
        int oc = idx & 255, k = idx >> 8;
        float v = w4[oc * 2304 + k];
        g_wt4[idx] = pack2(v, v);
        return;
    }
    idx -= NT3;
    if (idx < NTH) {
        int slot = idx & 63, k = idx >> 6;
        float v = 0.0f;
        if (slot < 12) v = wcls[slot * 2304 + k];
        else if (slot < 60) v = wbox[(slot - 12) * 2304 + k];
        g_wth[idx] = pack2(v, v);
    }
}

// =====================================================================
// Kernel 1: 1x1 conv (512->256) + BN + ReLU.
// Half-image CTAs by position. smem [512][26] (53.2KB) -> 4 CTA/SM.
// 256 threads: ocpair = tid&127, sub = tid>>7. Writes clamped to half.
// =====================================================================
#define SM1_BYTES (512 * 26 * 4)

__global__ void __launch_bounds__(256, 4) k_conv1x1(
    const float* __restrict__ in, const ull* __restrict__ wt,
    const float* __restrict__ b, const float* __restrict__ g,
    const float* __restrict__ be, const float* __restrict__ mu,
    const float* __restrict__ var, float* __restrict__ out)
{
    extern __shared__ float sm[];
    const int blk = blockIdx.x;
    const int bidx = blk >> 1;
    const int half = blk & 1;
    const int tid = threadIdx.x;
    const float* inb = in + (size_t)bidx * 512 * 49;
    const int p0 = half ? 24 : 0;
    const int np = half ? 25 : 24;
    const int plimit = p0 + np;

    for (int k = tid; k < 512 * 13; k += 256) ((ull*)sm)[k] = 0ull;
    __syncthreads();
    for (int k = tid; k < 512 * np; k += 256) {
        int ic = k / np, p = k % np;
        sm[ic * 26 + p] = inb[ic * 49 + p0 + p];
    }
    __syncthreads();

    const int op = tid & 127;
    const int sub = tid >> 7;
    const int oc0 = op * 2;
    const int pp0 = sub ? 7 : 0;
    const int pn = sub ? 6 : 7;

    ull acc[2][7];
#pragma unroll
    for (int j = 0; j < 2; j++)
#pragma unroll
        for (int p = 0; p < 7; p++) acc[j][p] = 0ull;

#pragma unroll 1
    for (int ic = 0; ic < 512; ic++) {
        ulonglong2 wv = *(const ulonglong2*)(wt + ic * 256 + oc0);
        const ull* row = (const ull*)(sm + ic * 26) + pp0;
#pragma unroll
        for (int p = 0; p < 7; p++) {
            if (sub == 0 || p < 6) {
                ull x = row[p];
                acc[0][p] = fma2(wv.x, x, acc[0][p]);
                acc[1][p] = fma2(wv.y, x, acc[1][p]);
            }
        }
    }

#pragma unroll
    for (int j = 0; j < 2; j++) {
        int oc = oc0 + j;
        float inv = g[oc] * rsqrtf(var[oc] + 1e-5f);
        float sh = (b[oc] - mu[oc]) * inv + be[oc];
        float* outp = out + (size_t)bidx * 256 * 49 + oc * 49;
#pragma unroll
        for (int p = 0; p < 7; p++) {
            if (p < pn) {
                float vlo, vhi;
                unpack2(acc[j][p], vlo, vhi);
                int pos = p0 + 2 * (pp0 + p);
                if (pos < plimit) outp[pos] = fmaxf(vlo * inv + sh, 0.0f);
                if (pos + 1 < plimit) outp[pos + 1] = fmaxf(vhi * inv + sh, 0.0f);
            }
        }
    }
}

// =====================================================================
// Kernel 2: 3x3 conv (256->256, pad 1) + BN + ReLU.
// Column-half CTAs, E/O dual tile, TWO-PHASE over ic (tile 35KB ->
// 4 CTA/SM, grid 512 = one wave).
// NEW: NO pad MACs anywhere. half0: out0 (2 scalar taps) + out1
// (3 scalar taps) + pair(2,3); half1: pair(4,5) + out6 (2 scalar taps).
// Dropped terms are all w*(+0) additions (acc never -0) -> bit-exact.
// FMA order ic->dy->dx preserved.
// =====================================================================
#define SM3_BYTES (128 * 70 * 4)

__global__ void __launch_bounds__(256, 4) k_conv3x3(
    const float* __restrict__ in, const ull* __restrict__ wt,
    const float* __restrict__ b, const float* __restrict__ g,
    const float* __restrict__ be, const float* __restrict__ mu,
    const float* __restrict__ var, float* __restrict__ out)
{
    extern __shared__ float sm[];
    const int blk = blockIdx.x;
    const int bidx = blk >> 1;
    const int half = blk & 1;
    const int tid = threadIdx.x;
    const float* inb = in + (size_t)bidx * 256 * 49;

    const int cw = half ? 4 : 5;       // valid cols to load
    const int coff = half ? 0 : 1;     // first valid tile col
    const int xoff = half ? 3 : 0;     // input x of first valid col

    for (int k = tid; k < 128 * 35; k += 256) ((ull*)sm)[k] = 0ull;

    const int oc = tid;
    ull accP[7];          // half0: pair(2,3); half1: pair(4,5)
    float aLo[7], aHi[7]; // half0: out0,out1 ; half1: aLo = out6
#pragma unroll
    for (int y = 0; y < 7; y++) {
        accP[y] = 0ull;
        aLo[y] = 0.0f;
        aHi[y] = 0.0f;
    }

    const int nload = 128 * 7 * cw;

#pragma unroll 1
    for (int ph = 0; ph < 2; ph++) {
        __syncthreads();   // prior-phase compute (or zeroing) done
        const float* inph = inb + ph * 128 * 49;
        for (int k = tid; k < nload; k += 256) {
            int icl = k / (7 * cw), rem = k % (7 * cw);
            int r = rem / cw, j = rem % cw;
            float v = inph[icl * 49 + r * 7 + xoff + j];
            int base = icl * 70 + r * 10;
            int cpos = coff + j;
            sm[base + cpos] = v;                                      // E: c0..c5
            if (cpos >= 1 && cpos <= 4) sm[base + 6 + (cpos - 1)] = v;   // O: c1..c4
        }
        __syncthreads();

        const ull* wtp = wt + (size_t)ph * 128 * 9 * 256 + oc;
        if (half == 0) {
            // tile: c0=pad, c1..c5 = x0..x4. E1=(x1,x2) E2=(x3,x4)
            // O0=(x0,x1) O1=(x2,x3). out0/out1 scalar, pair(2,3) packed.
#pragma unroll 1
            for (int icl = 0; icl < 128; icl++) {
                ull wc[9];
#pragma unroll
                for (int t = 0; t < 9; t++) wc[t] = __ldg(wtp + (icl * 9 + t) * 256);

                const ull* rowb = (const ull*)sm + icl * 35;
#pragma unroll
                for (int r = 0; r < 7; r++) {
                    ull E1 = rowb[r * 5 + 1], E2 = rowb[r * 5 + 2];
                    ull O0 = rowb[r * 5 + 3], O1 = rowb[r * 5 + 4];
                    float x0 = lo32f(O0), x1 = hi32f(O0), x2 = hi32f(E1);
#pragma unroll
                    for (int dy = 0; dy < 3; dy++) {
                        int yy = r - dy + 1;
                        if (yy < 0 || yy > 6) continue;
                        float w0 = lo32f(wc[dy * 3 + 0]);
                        float w1 = lo32f(wc[dy * 3 + 1]);
                        float w2 = lo32f(wc[dy * 3 + 2]);
                        // out0: (w0*pad dropped) w1*x0, w2*x1
                        aLo[yy] = fmaf(w1, x0, aLo[yy]);
                        aLo[yy] = fmaf(w2, x1, aLo[yy]);
                        // out1: w0*x0, w1*x1, w2*x2
                        aHi[yy] = fmaf(w0, x0, aHi[yy]);
                        aHi[yy] = fmaf(w1, x1, aHi[yy]);
                        aHi[yy] = fmaf(w2, x2, aHi[yy]);
                        // pair (2,3)
                        accP[yy] = fma2(wc[dy * 3 + 0], E1, accP[yy]);
                        accP[yy] = fma2(wc[dy * 3 + 1], O1, accP[yy]);
                        accP[yy] = fma2(wc[dy * 3 + 2], E2, accP[yy]);
                    }
                }
            }
        } else {
            // tile: c0..c3 = x3..x6. E0=(x3,x4) O0=(x4,x5) E1=(x5,x6).
            // pair(4,5) packed; out6: w0*x5, w1*x6 (w2*pad dropped).
#pragma unroll 1
            for (int icl = 0; icl < 128; icl++) {
                ull wc[9];
#pragma unroll
                for (int t = 0; t < 9; t++) wc[t] = __ldg(wtp + (icl * 9 + t) * 256);

                const ull* rowb = (const ull*)sm + icl * 35;
#pragma unroll
                for (int r = 0; r < 7; r++) {
                    ull E0 = rowb[r * 5 + 0], E1 = rowb[r * 5 + 1];
                    ull O0 = rowb[r * 5 + 3];
                    float x5 = lo32f(E1), x6 = hi32f(E1);
#pragma unroll
                    for (int dy = 0; dy < 3; dy++) {
                        int yy = r - dy + 1;
                        if (yy < 0 || yy > 6) continue;
                        accP[yy] = fma2(wc[dy * 3 + 0], E0, accP[yy]);
                        accP[yy] = fma2(wc[dy * 3 + 1], O0, accP[yy]);
                        accP[yy] = fma2(wc[dy * 3 + 2], E1, accP[yy]);
                        aLo[yy] = fmaf(lo32f(wc[dy * 3 + 0]), x5, aLo[yy]);
                        aLo[yy] = fmaf(lo32f(wc[dy * 3 + 1]), x6, aLo[yy]);
                    }
                }
            }
        }
    }

    float inv = g[oc] * rsqrtf(var[oc] + 1e-5f);
    float sh = (b[oc] - mu[oc]) * inv + be[oc];
    float* outp = out + (size_t)bidx * 256 * 49 + oc * 49;
    if (half == 0) {
#pragma unroll
        for (int yy = 0; yy < 7; yy++) {
            outp[yy * 7 + 0] = fmaxf(aLo[yy] * inv + sh, 0.0f);
            outp[yy * 7 + 1] = fmaxf(aHi[yy] * inv + sh, 0.0f);
            float vlo, vhi;
            unpack2(accP[yy], vlo, vhi);
            outp[yy * 7 + 2] = fmaxf(vlo * inv + sh, 0.0f);
            outp[yy * 7 + 3] = fmaxf(vhi * inv + sh, 0.0f);
        }
    } else {
#pragma unroll
        for (int yy = 0; yy < 7; yy++) {
            float vlo, vhi;
            unpack2(accP[yy], vlo, vhi);
            outp[yy * 7 + 4] = fmaxf(vlo * inv + sh, 0.0f);
            outp[yy * 7 + 5] = fmaxf(vhi * inv + sh, 0.0f);
            outp[yy * 7 + 6] = fmaxf(aLo[yy] * inv + sh, 0.0f);
        }
    }
}

// =====================================================================
// Kernel 3: heads — 3x3 conv into 12 cls + 48 box channels (+bias).
// Half-image CTAs by row, E/O dual-layout rows, TWO-PHASE over ic:
// tile [128 ic][6 rows][18 floats] = 54KB -> 4 CTA/SM, grid 512 = 1 wave.
// 3 f32x2 pairs (x0..5) + scalar for x6 (pad tap dropped). Bit-exact.
// =====================================================================
#define SMH_BYTES (128 * 108 * 4)

__global__ void __launch_bounds__(256, 4) k_heads(
    const float* __restrict__ in, const ull* __restrict__ wt,
    const float* __restrict__ bcls, const float* __restrict__ bbox,
    float* __restrict__ boxpred, float* __restrict__ scores)
{
    extern __shared__ float sm[];
    const int blk = blockIdx.x;
    const int bidx = blk >> 1;
    const int half = blk & 1;
    const int tid = threadIdx.x;
    const float* inb = in + (size_t)bidx * 256 * 49;
    const int base = half ? 3 : -1;      // smem row r = input row base+r
    const int outbase = half ? 4 : 0;

    for (int k = tid; k < 128 * 54; k += 256) ((ull*)sm)[k] = 0ull;

    const int slot = tid & 63;
    const int lr = tid >> 6;      // 0..3
    const int yout = outbase + lr;
    const bool valid = (yout < 7);

    ull acc[3];
    float accS = 0.0f;
#pragma unroll
    for (int k2 = 0; k2 < 3; k2++) acc[k2] = 0ull;

#pragma unroll 1
    for (int ph = 0; ph < 2; ph++) {
        __syncthreads();
        const float* inph = inb + ph * 128 * 49;
        for (int k = tid; k < 128 * 42; k += 256) {
            int icl = k / 42, rem = k % 42, r = rem / 7, x = rem % 7;
            int y = base + r;
            if (y >= 0 && y <= 6) {
                float v = inph[icl * 49 + y * 7 + x];
                int rbase = icl * 108 + r * 18;
                sm[rbase + x + 1] = v;        // E slots (value x at offset x+1)
                sm[rbase + 10 + x] = v;       // O slots (value x at offset 10+x)
            }
        }
        __syncthreads();

        if (valid) {
            const ull* wtp = wt + (size_t)ph * 128 * 9 * 64 + slot;
#pragma unroll 1
            for (int icl = 0; icl < 128; icl++) {
                ull wc[9];
#pragma unroll
                for (int t = 0; t < 9; t++) wc[t] = __ldg(wtp + (icl * 9 + t) * 64);

#pragma unroll
                for (int dy = 0; dy < 3; dy++) {
                    int r = lr + dy;
                    const ull* rp = (const ull*)(sm + icl * 108 + r * 18);
                    ull E0 = rp[0], E1 = rp[1], E2 = rp[2], E3 = rp[3];
                    ull O0 = rp[5], O1 = rp[6], O2 = rp[7];
                    float x5 = lo32f(E3), x6 = hi32f(E3);
                    acc[0] = fma2(wc[dy * 3 + 0], E0, acc[0]);
                    acc[0] = fma2(wc[dy * 3 + 1], O0, acc[0]);
                    acc[0] = fma2(wc[dy * 3 + 2], E1, acc[0]);
                    acc[1] = fma2(wc[dy * 3 + 0], E1, acc[1]);
                    acc[1] = fma2(wc[dy * 3 + 1], O1, acc[1]);
                    acc[1] = fma2(wc[dy * 3 + 2], E2, acc[1]);
                    acc[2] = fma2(wc[dy * 3 + 0], E2, acc[2]);
                    acc[2] = fma2(wc[dy * 3 + 1], O2, acc[2]);
                    acc[2] = fma2(wc[dy * 3 + 2], E3, acc[2]);
                    accS = fmaf(lo32f(wc[dy * 3 + 0]), x5, accS);
                    accS = fmaf(lo32f(wc[dy * 3 + 1]), x6, accS);
                }
            }
        }
    }

    if (!valid) return;

    if (slot < 12) {
        float bv = bcls[slot];
#pragma unroll
        for (int k2 = 0; k2 < 3; k2++) {
            float vlo, vhi;
            unpack2(acc[k2], vlo, vhi);
            int x = 2 * k2;
            int p0 = yout * 7 + x;
            scores[(size_t)bidx * 588 + p0 * 12 + slot] = xla_sigmoid(vlo + bv);
            scores[(size_t)bidx * 588 + (p0 + 1) * 12 + slot] = xla_sigmoid(vhi + bv);
        }
        scores[(size_t)bidx * 588 + (yout * 7 + 6) * 12 + slot] = xla_sigmoid(accS + bv);
    } else if (slot < 60) {
        int c = slot - 12;
        int a = c >> 2, coord = c & 3;
        float bv = bbox[c];
#pragma unroll
        for (int k2 = 0; k2 < 3; k2++) {
            float vlo, vhi;
            unpack2(acc[k2], vlo, vhi);
            int x = 2 * k2;
            int p0 = yout * 7 + x;
            boxpred[((size_t)bidx * 588 + p0 * 12 + a) * 4 + coord] = vlo + bv;
            boxpred[((size_t)bidx * 588 + (p0 + 1) * 12 + a) * 4 + coord] = vhi + bv;
        }
        boxpred[((size_t)bidx * 588 + (yout * 7 + 6) * 12 + a) * 4 + coord] = accS + bv;
    }
}

// =====================================================================
// Kernel 4: decode + exact greedy NMS. One block (256 thr) per image.
// =====================================================================
#define SMN_BYTES (6468 * 4 + 588 * 8 + 588 * 19 * 4 + 101 * 4)

__global__ void __launch_bounds__(256) k_nms(
    const float* __restrict__ boxpred, const float* __restrict__ scores,
    float* __restrict__ out)
{
    extern __shared__ float sm[];
    float* dbx = sm;
    float* dsc = dbx + 2352;
    float* sbx = dsc + 588;
    float* ss = sbx + 2352;
    float* sar = ss + 588;
    ull* keys = (ull*)(sar + 588);
    unsigned* adj = (unsigned*)(keys + 588);
    int* keepL = (int*)(adj + 588 * 19);
    int* keepCnt = keepL + 100;

    const int bidx = blockIdx.x;
    const int tid = threadIdx.x;
    const float* bp = boxpred + (size_t)bidx * 588 * 4;
    const float* sc = scores + (size_t)bidx * 588;

    const float SCALES[4] = {0.3f, 0.5f, 0.7f, 0.9f};
    const float RATIOS[3] = {0.7f, 1.0f, 1.3f};

    for (int i = tid; i < 588; i += 256) {
        int p = i / 12, a = i % 12;
        int si = a / 3, ri = a % 3;
        float cx = ((float)(p / 7) + 0.5f) / 7.0f;
        float cy = ((float)(p % 7) + 0.5f) / 7.0f;
        float rt = sqrtf(RATIOS[ri]);
        float ws = SCALES[si] * rt;
        float hs = SCALES[si] / rt;
        float hw = ws * 0.5f, hh = hs * 0.5f;
        float a0 = cx - hw, a1 = cy - hh, a2 = cx + hw, a3 = cy + hh;
        float acx = (a0 + a2) * 0.5f, acy = (a1 + a3) * 0.5f;
        float aszx = a2 - a0, aszy = a3 - a1;
        float t0 = bp[i * 4 + 0], t1 = bp[i * 4 + 1];
        float t2 = bp[i * 4 + 2], t3 = bp[i * 4 + 3];
        float pcx = t0 * aszx + acx;
        float pcy = t1 * aszy + acy;
        float psx = expf(t2) * aszx;
        float psy = expf(t3) * aszy;
        dbx[i * 4 + 0] = pcx - psx * 0.5f;
        dbx[i * 4 + 1] = pcy - psy * 0.5f;
        dbx[i * 4 + 2] = pcx + psx * 0.5f;
        dbx[i * 4 + 3] = pcy + psy * 0.5f;
        float s = sc[i];
        dsc[i] = s;
        keys[i] = (((ull)(0xFFFFFFFFu - __float_as_uint(s))) << 32) | (unsigned)i;
    }
    __syncthreads();

    for (int i = tid; i < 588; i += 256) {
        ull ki = keys[i];
        int r = 0;
        for (int j = 0; j < 588; j++) r += (keys[j] < ki) ? 1 : 0;
        ss[r] = dsc[i];
        float x0 = dbx[i * 4 + 0], y0 = dbx[i * 4 + 1];
        float x1 = dbx[i * 4 + 2], y1 = dbx[i * 4 + 3];
        sbx[r * 4 + 0] = x0;
        sbx[r * 4 + 1] = y0;
        sbx[r * 4 + 2] = x1;
        sbx[r * 4 + 3] = y1;
        sar[r] = (x1 - x0) * (y1 - y0);
    }
    __syncthreads();

    for (int t = tid; t < 588 * 19; t += 256) {
        int i = t / 19, wdi = t % 19;
        unsigned word = 0;
        if (ss[i] > CONF_THR) {
            float ax0 = sbx[i * 4 + 0], ay0 = sbx[i * 4 + 1];
            float ax1 = sbx[i * 4 + 2], ay1 = sbx[i * 4 + 3];
            float aar = sar[i];
            int j0 = wdi * 32;
            int jend = min(588 - j0, 32);
            for (int bb = 0; bb < jend; bb++) {
                int j = j0 + bb;
                float lx = fmaxf(ax0, sbx[j * 4 + 0]);
                float ly = fmaxf(ay0, sbx[j * 4 + 1]);
                float rx = fminf(ax1, sbx[j * 4 + 2]);
                float ry = fminf(ay1, sbx[j * 4 + 3]);
                float iw = fmaxf(rx - lx, 0.0f);
                float ih = fmaxf(ry - ly, 0.0f);
                float inter = iw * ih;
                float iou = inter / (aar + sar[j] - inter + 1e-9f);
                if (iou > NMS_THRV) word |= (1u << bb);
            }
        }
        adj[i * 19 + wdi] = word;
    }
    __syncthreads();

    if (tid == 0) {
        unsigned sup[19];
#pragma unroll
        for (int w2 = 0; w2 < 19; w2++) sup[w2] = 0u;
        int cnt = 0;
        for (int i = 0; i < 588; i++) {
            if (!(ss[i] > CONF_THR)) break;
            if ((sup[i >> 5] >> (i & 31)) & 1u) continue;
            keepL[cnt++] = i;
            if (cnt == MAXDET) break;
            int w0 = i >> 5, bpos = i & 31;
            unsigned m0 = (bpos == 31) ? 0u : (0xFFFFFFFFu << (bpos + 1));
            sup[w0] |= adj[i * 19 + w0] & m0;
            for (int w2 = w0 + 1; w2 < 19; w2++) sup[w2] |= adj[i * 19 + w2];
        }
        *keepCnt = cnt;
    }
    __syncthreads();

    int cnt = *keepCnt;
    for (int r = tid; r < MAXDET; r += 256) {
        float* o = out + ((size_t)bidx * MAXDET + r) * 6;
        if (r < cnt) {
            int i = keepL[r];
            o[0] = sbx[i * 4 + 0];
            o[1] = sbx[i * 4 + 1];
            o[2] = sbx[i * 4 + 2];
            o[3] = sbx[i * 4 + 3];
            o[4] = ss[i];
            o[5] = 1.0f;
        } else {
            o[0] = 0.0f; o[1] = 0.0f; o[2] = 0.0f;
            o[3] = 0.0f; o[4] = 0.0f; o[5] = 0.0f;
        }
    }
}

// =====================================================================
// launcher
// =====================================================================
extern "C" void kernel_launch(void* const* d_in, const int* in_sizes, int n_in,
                              void* d_out, int out_size)
{
    (void)in_sizes; (void)n_in; (void)out_size;

    const float* features = (const float*)d_in[0];
    const float* w1 = (const float*)d_in[1];
    const float* b1 = (const float*)d_in[2];
    const float* g1 = (const float*)d_in[3];
    const float* be1 = (const float*)d_in[4];
    const float* mu1 = (const float*)d_in[5];
    const float* var1 = (const float*)d_in[6];
    const float* w2 = (const float*)d_in[7];
    const float* b2 = (const float*)d_in[8];
    const float* g2 = (const float*)d_in[9];
    const float* be2 = (const float*)d_in[10];
    const float* mu2 = (const float*)d_in[11];
    const float* var2 = (const float*)d_in[12];
    const float* w3 = (const float*)d_in[13];
    const float* b3 = (const float*)d_in[14];
    const float* g3 = (const float*)d_in[15];
    const float* be3 = (const float*)d_in[16];
    const float* mu3 = (const float*)d_in[17];
    const float* var3 = (const float*)d_in[18];
    const float* w4 = (const float*)d_in[19];
    const float* b4 = (const float*)d_in[20];
    const float* g4 = (const float*)d_in[21];
    const float* be4 = (const float*)d_in[22];
    const float* mu4 = (const float*)d_in[23];
    const float* var4 = (const float*)d_in[24];
    const float* w_cls = (const float*)d_in[25];
    const float* b_cls = (const float*)d_in[26];
    const float* w_box = (const float*)d_in[27];
    const float* b_box = (const float*)d_in[28];
    float* out = (float*)d_out;

    float *act0, *act1, *bpred, *scr;
    ull *wt1, *wt2, *wt3, *wt4, *wth;
    cudaGetSymbolAddress((void**)&act0, g_act0);
    cudaGetSymbolAddress((void**)&act1, g_act1);
    cudaGetSymbolAddress((void**)&bpred, g_boxpred);
    cudaGetSymbolAddress((void**)&scr, g_scores);
    cudaGetSymbolAddress((void**)&wt1, g_wt1);
    cudaGetSymbolAddress((void**)&wt2, g_wt2);
    cudaGetSymbolAddress((void**)&wt3, g_wt3);
    cudaGetSymbolAddress((void**)&wt4, g_wt4);
    cudaGetSymbolAddress((void**)&wth, g_wth);

    cudaFuncSetAttribute(k_conv1x1, cudaFuncAttributeMaxDynamicSharedMemorySize, SM1_BYTES);
    cudaFuncSetAttribute(k_conv3x3, cudaFuncAttributeMaxDynamicSharedMemorySize, SM3_BYTES);
    cudaFuncSetAttribute(k_heads, cudaFuncAttributeMaxDynamicSharedMemorySize, SMH_BYTES);
    cudaFuncSetAttribute(k_nms, cudaFuncAttributeMaxDynamicSharedMemorySize, SMN_BYTES);

    k_wt<<<(NT_TOTAL + 255) / 256, 256>>>(w1, w2, w3, w4, w_cls, w_box);
    k_conv1x1<<<512, 256, SM1_BYTES>>>(features, wt1, b1, g1, be1, mu1, var1, act0);
    k_conv3x3<<<512, 256, SM3_BYTES>>>(act0, wt2, b2, g2, be2, mu2, var2, act1);
    k_conv3x3<<<512, 256, SM3_BYTES>>>(act1, wt3, b3, g3, be3, mu3, var3, act0);
    k_conv3x3<<<512, 256, SM3_BYTES>>>(act0, wt4, b4, g4, be4, mu4, var4, act1);
    k_heads<<<512, 256, SMH_BYTES>>>(act1, wth, b_cls, b_box, bpred, scr);
    k_nms<<<256, 256, SMN_BYTES>>>(bpred, scr, out);
}